// round 1
// baseline (speedup 1.0000x reference)
#include <cuda_runtime.h>
#include <math.h>

#define B_ 2
#define T_ 2048
#define D_ 2048
#define H_ 16
#define HD_ 128
#define BT_ (B_ * T_)
#define BTD_ (B_ * T_ * D_)

// Scratch: xn, q, k, v, attn_out  (5 x 32MB = 160MB)
__device__ float g_scratch[5ull * BTD_];

// ---------------------------------------------------------------------------
// RMSNorm: one block per row of D=2048
// ---------------------------------------------------------------------------
__global__ void __launch_bounds__(256) rmsnorm_kernel(
    const float* __restrict__ x, const float* __restrict__ w, float* __restrict__ out)
{
    const int row = blockIdx.x;
    const float4* xr = (const float4*)(x + (size_t)row * D_);
    float4* orow = (float4*)(out + (size_t)row * D_);
    const float4* w4 = (const float4*)w;
    const int tid = threadIdx.x;

    float4 v0 = xr[tid];
    float4 v1 = xr[tid + 256];
    float ss = v0.x*v0.x + v0.y*v0.y + v0.z*v0.z + v0.w*v0.w
             + v1.x*v1.x + v1.y*v1.y + v1.z*v1.z + v1.w*v1.w;

    #pragma unroll
    for (int m = 16; m > 0; m >>= 1) ss += __shfl_xor_sync(0xffffffffu, ss, m);

    __shared__ float red[8];
    if ((tid & 31) == 0) red[tid >> 5] = ss;
    __syncthreads();
    float tot = red[0] + red[1] + red[2] + red[3] + red[4] + red[5] + red[6] + red[7];

    // norm = sqrt(sumsq) * D^-0.5 ; out = w * x / (norm + eps)
    const float inv = 1.0f / (sqrtf(tot) * 0.022097086912079612f + 1e-8f);

    float4 w0 = w4[tid], w1 = w4[tid + 256];
    float4 o0, o1;
    o0.x = v0.x * w0.x * inv; o0.y = v0.y * w0.y * inv;
    o0.z = v0.z * w0.z * inv; o0.w = v0.w * w0.w * inv;
    o1.x = v1.x * w1.x * inv; o1.y = v1.y * w1.y * inv;
    o1.z = v1.z * w1.z * inv; o1.w = v1.w * w1.w * inv;
    orow[tid] = o0;
    orow[tid + 256] = o1;
}

// ---------------------------------------------------------------------------
// SGEMM: C = A @ W^T   (A:[M,K] row-major, W:[N,K] row-major)
// 128x128 block tile, BK=8, 256 threads, 8x8 register tile, double-buffered.
// mode 0: store into [B,H,T,HD] qkv layout (BN==HD so head == blockIdx.x)
// mode 1: store plain [M,N] row-major
// ---------------------------------------------------------------------------
__global__ void __launch_bounds__(256) gemm_kernel(
    const float* __restrict__ A, const float* __restrict__ W,
    float* __restrict__ C, int K, int N, int mode)
{
    __shared__ float As[2][8][128];
    __shared__ float Bs[2][8][128];

    const int tid = threadIdx.x;
    const int bm = blockIdx.y, bn = blockIdx.x;

    const int arow = tid >> 1;          // 0..127
    const int acol = (tid & 1) << 2;    // 0 or 4
    const float* Ap = A + (size_t)(bm * 128 + arow) * K + acol;
    const float* Wp = W + (size_t)(bn * 128 + arow) * K + acol;

    const int ty = tid >> 4;            // 0..15 -> rows
    const int tx = tid & 15;            // 0..15 -> cols

    float acc[8][8];
    #pragma unroll
    for (int i = 0; i < 8; ++i)
        #pragma unroll
        for (int j = 0; j < 8; ++j) acc[i][j] = 0.0f;

    float4 a4 = *(const float4*)Ap;
    float4 b4 = *(const float4*)Wp;
    As[0][acol + 0][arow] = a4.x; As[0][acol + 1][arow] = a4.y;
    As[0][acol + 2][arow] = a4.z; As[0][acol + 3][arow] = a4.w;
    Bs[0][acol + 0][arow] = b4.x; Bs[0][acol + 1][arow] = b4.y;
    Bs[0][acol + 2][arow] = b4.z; Bs[0][acol + 3][arow] = b4.w;
    __syncthreads();

    const int nk = K >> 3;
    for (int kt = 0; kt < nk; ++kt) {
        const int cur = kt & 1;
        if (kt + 1 < nk) {
            a4 = *(const float4*)(Ap + (kt + 1) * 8);
            b4 = *(const float4*)(Wp + (kt + 1) * 8);
        }
        #pragma unroll
        for (int k = 0; k < 8; ++k) {
            float ar[8], br[8];
            *(float4*)&ar[0] = *(const float4*)&As[cur][k][ty * 8];
            *(float4*)&ar[4] = *(const float4*)&As[cur][k][ty * 8 + 4];
            *(float4*)&br[0] = *(const float4*)&Bs[cur][k][tx * 8];
            *(float4*)&br[4] = *(const float4*)&Bs[cur][k][tx * 8 + 4];
            #pragma unroll
            for (int i = 0; i < 8; ++i)
                #pragma unroll
                for (int j = 0; j < 8; ++j)
                    acc[i][j] += ar[i] * br[j];
        }
        if (kt + 1 < nk) {
            const int nxt = cur ^ 1;
            As[nxt][acol + 0][arow] = a4.x; As[nxt][acol + 1][arow] = a4.y;
            As[nxt][acol + 2][arow] = a4.z; As[nxt][acol + 3][arow] = a4.w;
            Bs[nxt][acol + 0][arow] = b4.x; Bs[nxt][acol + 1][arow] = b4.y;
            Bs[nxt][acol + 2][arow] = b4.z; Bs[nxt][acol + 3][arow] = b4.w;
            __syncthreads();
        }
    }

    if (mode == 0) {
        // q/k/v layout: offset = ((b*H + h)*T + t)*HD + hd, h == bn, hd = tx*8+j
        #pragma unroll
        for (int i = 0; i < 8; ++i) {
            const int gm = bm * 128 + ty * 8 + i;
            const int b = gm >> 11;       // / T_
            const int t = gm & (T_ - 1);
            float* cp = C + (((size_t)(b * H_ + bn) * T_) + t) * HD_ + tx * 8;
            *(float4*)cp       = make_float4(acc[i][0], acc[i][1], acc[i][2], acc[i][3]);
            *(float4*)(cp + 4) = make_float4(acc[i][4], acc[i][5], acc[i][6], acc[i][7]);
        }
    } else {
        #pragma unroll
        for (int i = 0; i < 8; ++i) {
            const int gm = bm * 128 + ty * 8 + i;
            float* cp = C + (size_t)gm * N + bn * 128 + tx * 8;
            *(float4*)cp       = make_float4(acc[i][0], acc[i][1], acc[i][2], acc[i][3]);
            *(float4*)(cp + 4) = make_float4(acc[i][4], acc[i][5], acc[i][6], acc[i][7]);
        }
    }
}

// ---------------------------------------------------------------------------
// Flash attention (fp32, causal). 64 q-rows x 64 kv-rows tiles, HD=128.
// 256 threads: rg = tid/16 -> 4 q-rows, cg = tid%16 -> 4 S-cols / 8 O-cols.
// Smem: Qt[128][64] (transposed, pre-scaled), Kt[128][64] (transposed),
//       Vs[64][128], Ps[64][68].
// ---------------------------------------------------------------------------
#define ATT_SMEM_FLOATS (3 * 8192 + 64 * 68)
#define ATT_SMEM_BYTES  (ATT_SMEM_FLOATS * 4)
#define ATT_SCALE 0.08838834764831845f   // 128^-0.5

__global__ void __launch_bounds__(256) attn_kernel(
    const float* __restrict__ Q, const float* __restrict__ K,
    const float* __restrict__ V, float* __restrict__ Out)
{
    extern __shared__ float sm[];
    float* Qt = sm;                 // [128][64]
    float* Kt = sm + 8192;          // [128][64]
    float* Vs = sm + 16384;         // [64][128]
    float* Ps = sm + 24576;         // [64][68]

    const int qtile = blockIdx.x;
    const int bh = blockIdx.y;
    const int b = bh >> 4;          // / H_
    const int h = bh & (H_ - 1);
    const int q0 = qtile * 64;
    const int tid = threadIdx.x;
    const int rg = tid >> 4;
    const int cg = tid & 15;

    const float* Qg = Q + ((size_t)bh * T_ + q0) * HD_;
    const float* Kg = K + (size_t)bh * T_ * HD_;
    const float* Vg = V + (size_t)bh * T_ * HD_;

    // Load Q tile transposed with softmax scale folded in
    #pragma unroll
    for (int it = 0; it < 8; ++it) {
        const int i = tid + it * 256;       // float4 index, 0..2047
        const int r = i >> 5;               // 32 float4 per row
        const int c4 = (i & 31) << 2;
        float4 qv = *(const float4*)(Qg + r * HD_ + c4);
        Qt[(c4 + 0) * 64 + r] = qv.x * ATT_SCALE;
        Qt[(c4 + 1) * 64 + r] = qv.y * ATT_SCALE;
        Qt[(c4 + 2) * 64 + r] = qv.z * ATT_SCALE;
        Qt[(c4 + 3) * 64 + r] = qv.w * ATT_SCALE;
    }

    float m_i[4], l_i[4], o[4][8];
    #pragma unroll
    for (int ii = 0; ii < 4; ++ii) {
        m_i[ii] = -INFINITY;
        l_i[ii] = 0.0f;
        #pragma unroll
        for (int hh = 0; hh < 8; ++hh) o[ii][hh] = 0.0f;
    }

    for (int kt = 0; kt <= qtile; ++kt) {
        const float* Kgt = Kg + (size_t)kt * 64 * HD_;
        const float* Vgt = Vg + (size_t)kt * 64 * HD_;

        __syncthreads();   // previous iteration done reading Kt/Vs/Ps (and Qt stored)
        #pragma unroll
        for (int it = 0; it < 8; ++it) {
            const int i = tid + it * 256;
            const int r = i >> 5;
            const int c4 = (i & 31) << 2;
            float4 kv = *(const float4*)(Kgt + r * HD_ + c4);
            Kt[(c4 + 0) * 64 + r] = kv.x;
            Kt[(c4 + 1) * 64 + r] = kv.y;
            Kt[(c4 + 2) * 64 + r] = kv.z;
            Kt[(c4 + 3) * 64 + r] = kv.w;
            *(float4*)(Vs + r * 128 + c4) = *(const float4*)(Vgt + r * HD_ + c4);
        }
        __syncthreads();

        // S = (Q*scale) @ K^T  (4x4 per thread)
        float s[4][4];
        #pragma unroll
        for (int ii = 0; ii < 4; ++ii)
            #pragma unroll
            for (int jj = 0; jj < 4; ++jj) s[ii][jj] = 0.0f;

        #pragma unroll 4
        for (int kk = 0; kk < 128; ++kk) {
            float4 qv = *(const float4*)(Qt + kk * 64 + rg * 4);
            float4 kv = *(const float4*)(Kt + kk * 64 + cg * 4);
            s[0][0] += qv.x * kv.x; s[0][1] += qv.x * kv.y; s[0][2] += qv.x * kv.z; s[0][3] += qv.x * kv.w;
            s[1][0] += qv.y * kv.x; s[1][1] += qv.y * kv.y; s[1][2] += qv.y * kv.z; s[1][3] += qv.y * kv.w;
            s[2][0] += qv.z * kv.x; s[2][1] += qv.z * kv.y; s[2][2] += qv.z * kv.z; s[2][3] += qv.z * kv.w;
            s[3][0] += qv.w * kv.x; s[3][1] += qv.w * kv.y; s[3][2] += qv.w * kv.z; s[3][3] += qv.w * kv.w;
        }

        if (kt == qtile) {          // diagonal tile: causal mask (local indices, q0 == kv0)
            #pragma unroll
            for (int ii = 0; ii < 4; ++ii)
                #pragma unroll
                for (int jj = 0; jj < 4; ++jj)
                    if (cg * 4 + jj > rg * 4 + ii) s[ii][jj] = -1e30f;
        }

        // Online softmax (row reductions over the 16 cg threads via half-warp shfl)
        #pragma unroll
        for (int ii = 0; ii < 4; ++ii) {
            float mx = fmaxf(fmaxf(s[ii][0], s[ii][1]), fmaxf(s[ii][2], s[ii][3]));
            #pragma unroll
            for (int off = 1; off < 16; off <<= 1)
                mx = fmaxf(mx, __shfl_xor_sync(0xffffffffu, mx, off));
            const float mnew = fmaxf(m_i[ii], mx);
            const float corr = __expf(m_i[ii] - mnew);
            m_i[ii] = mnew;
            float rs = 0.0f;
            #pragma unroll
            for (int jj = 0; jj < 4; ++jj) {
                const float p = __expf(s[ii][jj] - mnew);
                s[ii][jj] = p;
                rs += p;
            }
            #pragma unroll
            for (int off = 1; off < 16; off <<= 1)
                rs += __shfl_xor_sync(0xffffffffu, rs, off);
            l_i[ii] = l_i[ii] * corr + rs;
            #pragma unroll
            for (int hh = 0; hh < 8; ++hh) o[ii][hh] *= corr;
            *(float4*)(Ps + (rg * 4 + ii) * 68 + cg * 4) =
                make_float4(s[ii][0], s[ii][1], s[ii][2], s[ii][3]);
        }
        __syncthreads();

        // O += P @ V  (4 rows x 8 hd-cols per thread)
        #pragma unroll 2
        for (int j = 0; j < 64; ++j) {
            float4 v0 = *(const float4*)(Vs + j * 128 + cg * 8);
            float4 v1 = *(const float4*)(Vs + j * 128 + cg * 8 + 4);
            #pragma unroll
            for (int ii = 0; ii < 4; ++ii) {
                const float p = Ps[(rg * 4 + ii) * 68 + j];
                o[ii][0] += p * v0.x; o[ii][1] += p * v0.y;
                o[ii][2] += p * v0.z; o[ii][3] += p * v0.w;
                o[ii][4] += p * v1.x; o[ii][5] += p * v1.y;
                o[ii][6] += p * v1.z; o[ii][7] += p * v1.w;
            }
        }
    }

    // Epilogue: attn_out[b, t, h*HD + hd] with 1/l scaling
    #pragma unroll
    for (int ii = 0; ii < 4; ++ii) {
        const int r = rg * 4 + ii;
        const float inv = 1.0f / l_i[ii];
        float* op = Out + ((size_t)b * T_ + q0 + r) * D_ + h * HD_ + cg * 8;
        *(float4*)op = make_float4(o[ii][0] * inv, o[ii][1] * inv,
                                   o[ii][2] * inv, o[ii][3] * inv);
        *(float4*)(op + 4) = make_float4(o[ii][4] * inv, o[ii][5] * inv,
                                         o[ii][6] * inv, o[ii][7] * inv);
    }
}

// ---------------------------------------------------------------------------
// Launch
// ---------------------------------------------------------------------------
extern "C" void kernel_launch(void* const* d_in, const int* in_sizes, int n_in,
                              void* d_out, int out_size)
{
    const float* x  = (const float*)d_in[0];
    // d_in[1] = attn_mask (pure causal, computed in-kernel instead)
    const float* wn = (const float*)d_in[2];
    const float* wq = (const float*)d_in[3];
    const float* wk = (const float*)d_in[4];
    const float* wv = (const float*)d_in[5];
    const float* wo = (const float*)d_in[6];
    float* out = (float*)d_out;

    float* base = nullptr;
    cudaGetSymbolAddress((void**)&base, g_scratch);
    float* xn = base;
    float* qb = base + 1ull * BTD_;
    float* kb = base + 2ull * BTD_;
    float* vb = base + 3ull * BTD_;
    float* ao = base + 4ull * BTD_;

    rmsnorm_kernel<<<BT_, 256>>>(x, wn, xn);

    dim3 gg(D_ / 128, BT_ / 128);   // (16, 32)
    gemm_kernel<<<gg, 256>>>(xn, wq, qb, D_, D_, 0);
    gemm_kernel<<<gg, 256>>>(xn, wk, kb, D_, D_, 0);
    gemm_kernel<<<gg, 256>>>(xn, wv, vb, D_, D_, 0);

    cudaFuncSetAttribute(attn_kernel, cudaFuncAttributeMaxDynamicSharedMemorySize,
                         ATT_SMEM_BYTES);
    attn_kernel<<<dim3(T_ / 64, B_ * H_), 256, ATT_SMEM_BYTES>>>(qb, kb, vb, ao);

    gemm_kernel<<<gg, 256>>>(ao, wo, out, D_, D_, 1);
}

// round 3
// speedup vs baseline: 1.8934x; 1.8934x over previous
#include <cuda_runtime.h>
#include <math.h>
#include <stdint.h>

#define B_ 2
#define T_ 2048
#define D_ 2048
#define H_ 16
#define HD_ 128
#define BT_ (B_ * T_)
#define BTD_ (B_ * T_ * D_)

// Scratch: xn, q, k, v, attn_out  (5 x 32MB = 160MB)
__device__ float g_scratch[5ull * BTD_];

// ---------------------------------------------------------------------------
// helpers
// ---------------------------------------------------------------------------
__device__ __forceinline__ uint32_t smem_u32(const void* p) {
    uint32_t a;
    asm("{ .reg .u64 t; cvta.to.shared.u64 t, %1; cvt.u32.u64 %0, t; }"
        : "=r"(a) : "l"(p));
    return a;
}

__device__ __forceinline__ void cp16(uint32_t s, const void* g) {
    asm volatile("cp.async.cg.shared.global [%0], [%1], 16;"
                 :: "r"(s), "l"(g) : "memory");
}

__device__ __forceinline__ uint32_t cvt_tf32(float x) {
    uint32_t r;
    asm("cvt.rna.tf32.f32 %0, %1;" : "=r"(r) : "f"(x));
    return r;
}

__device__ __forceinline__ void mma_tf32(float* c, const uint32_t* a, const uint32_t* b) {
    asm volatile(
        "mma.sync.aligned.m16n8k8.row.col.f32.tf32.tf32.f32 "
        "{%0,%1,%2,%3}, {%4,%5,%6,%7}, {%8,%9}, {%0,%1,%2,%3};"
        : "+f"(c[0]), "+f"(c[1]), "+f"(c[2]), "+f"(c[3])
        : "r"(a[0]), "r"(a[1]), "r"(a[2]), "r"(a[3]), "r"(b[0]), "r"(b[1]));
}

// ---------------------------------------------------------------------------
// RMSNorm: one block per row of D=2048
// ---------------------------------------------------------------------------
__global__ void __launch_bounds__(256) rmsnorm_kernel(
    const float* __restrict__ x, const float* __restrict__ w, float* __restrict__ out)
{
    const int row = blockIdx.x;
    const float4* xr = (const float4*)(x + (size_t)row * D_);
    float4* orow = (float4*)(out + (size_t)row * D_);
    const float4* w4 = (const float4*)w;
    const int tid = threadIdx.x;

    float4 v0 = xr[tid];
    float4 v1 = xr[tid + 256];
    float ss = v0.x*v0.x + v0.y*v0.y + v0.z*v0.z + v0.w*v0.w
             + v1.x*v1.x + v1.y*v1.y + v1.z*v1.z + v1.w*v1.w;

    #pragma unroll
    for (int m = 16; m > 0; m >>= 1) ss += __shfl_xor_sync(0xffffffffu, ss, m);

    __shared__ float red[8];
    if ((tid & 31) == 0) red[tid >> 5] = ss;
    __syncthreads();
    float tot = red[0] + red[1] + red[2] + red[3] + red[4] + red[5] + red[6] + red[7];

    const float inv = 1.0f / (sqrtf(tot) * 0.022097086912079612f + 1e-8f);

    float4 w0 = w4[tid], w1 = w4[tid + 256];
    float4 o0, o1;
    o0.x = v0.x * w0.x * inv; o0.y = v0.y * w0.y * inv;
    o0.z = v0.z * w0.z * inv; o0.w = v0.w * w0.w * inv;
    o1.x = v1.x * w1.x * inv; o1.y = v1.y * w1.y * inv;
    o1.z = v1.z * w1.z * inv; o1.w = v1.w * w1.w * inv;
    orow[tid] = o0;
    orow[tid + 256] = o1;
}

// ---------------------------------------------------------------------------
// tf32 mma.sync GEMM: C = A @ W^T  (A:[M,2048], W:[2048,2048], both K-major)
// 128x128x32 CTA tile, 8 warps (2x4), warp tile 64x32 = 4x4 m16n8k8.
// Double-buffered cp.async. mode 0: qkv [B,H,T,HD] store; mode 1: row-major.
// ---------------------------------------------------------------------------
#define BK 32
#define LDW 36                         // BK + 4 pad (floats)
#define STAGE_FLOATS (128 * LDW)       // 4608 per matrix per stage
#define GEMM_SMEM_BYTES (4 * STAGE_FLOATS * 4)   // 73728
#define NKT 64                          // 2048 / 32

__global__ void __launch_bounds__(256, 2) gemm_mma(
    const float* __restrict__ A, const float* __restrict__ W,
    float* __restrict__ C, int mode)
{
    extern __shared__ float sm[];
    float* As = sm;                    // [2][128][36]
    float* Bs = sm + 2 * STAGE_FLOATS; // [2][128][36]

    const int tid = threadIdx.x;
    const int lane = tid & 31;
    const int wid = tid >> 5;
    const int wm = (wid & 1) * 64;     // warp m offset in tile
    const int wn = (wid >> 1) * 32;    // warp n offset in tile
    const int bm = blockIdx.y, bn = blockIdx.x;

    // gmem load geometry: chunk = tid + 256*i ; row = chunk/8, c4 = chunk%8
    const int r0 = tid >> 3;
    const int c4 = tid & 7;
    const float* Ag = A + (size_t)(bm * 128 + r0) * 2048 + c4 * 4;
    const float* Wg = W + (size_t)(bn * 128 + r0) * 2048 + c4 * 4;
    const uint32_t sA = smem_u32(As);
    const uint32_t sB = smem_u32(Bs);
    uint32_t soff[4];
    #pragma unroll
    for (int i = 0; i < 4; ++i)
        soff[i] = ((uint32_t)(r0 + 32 * i) * LDW + c4 * 4) * 4;

    float acc[4][4][4];
    #pragma unroll
    for (int mt = 0; mt < 4; ++mt)
        #pragma unroll
        for (int nt = 0; nt < 4; ++nt)
            #pragma unroll
            for (int q = 0; q < 4; ++q) acc[mt][nt][q] = 0.0f;

    // prologue: stage 0
    {
        const uint32_t a0 = sA, b0 = sB;
        #pragma unroll
        for (int i = 0; i < 4; ++i) cp16(a0 + soff[i], Ag + (size_t)(32 * i) * 2048);
        #pragma unroll
        for (int i = 0; i < 4; ++i) cp16(b0 + soff[i], Wg + (size_t)(32 * i) * 2048);
        asm volatile("cp.async.commit_group;" ::: "memory");
    }

    for (int kt = 0; kt < NKT; ++kt) {
        const int s = kt & 1;
        if (kt + 1 < NKT) {
            const int s1 = (kt + 1) & 1;
            const uint32_t a1 = sA + s1 * STAGE_FLOATS * 4;
            const uint32_t b1 = sB + s1 * STAGE_FLOATS * 4;
            const float* ag = Ag + (kt + 1) * 32;
            const float* wg = Wg + (kt + 1) * 32;
            #pragma unroll
            for (int i = 0; i < 4; ++i) cp16(a1 + soff[i], ag + (size_t)(32 * i) * 2048);
            #pragma unroll
            for (int i = 0; i < 4; ++i) cp16(b1 + soff[i], wg + (size_t)(32 * i) * 2048);
            asm volatile("cp.async.commit_group;" ::: "memory");
            asm volatile("cp.async.wait_group 1;" ::: "memory");
        } else {
            asm volatile("cp.async.wait_group 0;" ::: "memory");
        }
        __syncthreads();

        const float* Ast = As + s * STAGE_FLOATS;
        const float* Bst = Bs + s * STAGE_FLOATS;
        #pragma unroll
        for (int kk = 0; kk < 4; ++kk) {
            const int k = kk * 8;
            uint32_t a[4][4], b[4][2];
            #pragma unroll
            for (int mt = 0; mt < 4; ++mt) {
                const float* ap = Ast + (wm + mt * 16 + (lane >> 2)) * LDW + k + (lane & 3);
                a[mt][0] = cvt_tf32(ap[0]);
                a[mt][1] = cvt_tf32(ap[8 * LDW]);
                a[mt][2] = cvt_tf32(ap[4]);
                a[mt][3] = cvt_tf32(ap[8 * LDW + 4]);
            }
            #pragma unroll
            for (int nt = 0; nt < 4; ++nt) {
                const float* bp = Bst + (wn + nt * 8 + (lane >> 2)) * LDW + k + (lane & 3);
                b[nt][0] = cvt_tf32(bp[0]);
                b[nt][1] = cvt_tf32(bp[4]);
            }
            #pragma unroll
            for (int mt = 0; mt < 4; ++mt)
                #pragma unroll
                for (int nt = 0; nt < 4; ++nt)
                    mma_tf32(acc[mt][nt], a[mt], b[nt]);
        }
        __syncthreads();
    }

    // epilogue: c0,c1 at (row, col..col+1), c2,c3 at (row+8, col..col+1)
    const int rbase = bm * 128 + wm + (lane >> 2);
    const int cbase = wn + (lane & 3) * 2;
    #pragma unroll
    for (int mt = 0; mt < 4; ++mt) {
        #pragma unroll
        for (int half = 0; half < 2; ++half) {
            const int row = rbase + mt * 16 + half * 8;
            float* cp;
            if (mode == 0) {
                const int b = row >> 11;
                const int t = row & (T_ - 1);
                cp = C + (((size_t)(b * H_ + bn)) * T_ + t) * HD_ + cbase;
            } else {
                cp = C + (size_t)row * D_ + bn * 128 + cbase;
            }
            #pragma unroll
            for (int nt = 0; nt < 4; ++nt)
                *(float2*)(cp + nt * 8) =
                    make_float2(acc[mt][nt][half * 2], acc[mt][nt][half * 2 + 1]);
        }
    }
}

// ---------------------------------------------------------------------------
// Flash attention (fp32, causal). 64 q-rows x 64 kv-rows tiles, HD=128.
// ---------------------------------------------------------------------------
#define ATT_SMEM_FLOATS (3 * 8192 + 64 * 68)
#define ATT_SMEM_BYTES  (ATT_SMEM_FLOATS * 4)
#define ATT_SCALE 0.08838834764831845f

__global__ void __launch_bounds__(256) attn_kernel(
    const float* __restrict__ Q, const float* __restrict__ K,
    const float* __restrict__ V, float* __restrict__ Out)
{
    extern __shared__ float sm[];
    float* Qt = sm;                 // [128][64]
    float* Kt = sm + 8192;          // [128][64]
    float* Vs = sm + 16384;         // [64][128]
    float* Ps = sm + 24576;         // [64][68]

    const int qtile = blockIdx.x;
    const int bh = blockIdx.y;
    const int b = bh >> 4;
    const int h = bh & (H_ - 1);
    const int q0 = qtile * 64;
    const int tid = threadIdx.x;
    const int rg = tid >> 4;
    const int cg = tid & 15;

    const float* Qg = Q + ((size_t)bh * T_ + q0) * HD_;
    const float* Kg = K + (size_t)bh * T_ * HD_;
    const float* Vg = V + (size_t)bh * T_ * HD_;

    #pragma unroll
    for (int it = 0; it < 8; ++it) {
        const int i = tid + it * 256;
        const int r = i >> 5;
        const int c4v = (i & 31) << 2;
        float4 qv = *(const float4*)(Qg + r * HD_ + c4v);
        Qt[(c4v + 0) * 64 + r] = qv.x * ATT_SCALE;
        Qt[(c4v + 1) * 64 + r] = qv.y * ATT_SCALE;
        Qt[(c4v + 2) * 64 + r] = qv.z * ATT_SCALE;
        Qt[(c4v + 3) * 64 + r] = qv.w * ATT_SCALE;
    }

    float m_i[4], l_i[4], o[4][8];
    #pragma unroll
    for (int ii = 0; ii < 4; ++ii) {
        m_i[ii] = -INFINITY;
        l_i[ii] = 0.0f;
        #pragma unroll
        for (int hh = 0; hh < 8; ++hh) o[ii][hh] = 0.0f;
    }

    for (int kt = 0; kt <= qtile; ++kt) {
        const float* Kgt = Kg + (size_t)kt * 64 * HD_;
        const float* Vgt = Vg + (size_t)kt * 64 * HD_;

        __syncthreads();
        #pragma unroll
        for (int it = 0; it < 8; ++it) {
            const int i = tid + it * 256;
            const int r = i >> 5;
            const int c4v = (i & 31) << 2;
            float4 kv = *(const float4*)(Kgt + r * HD_ + c4v);
            Kt[(c4v + 0) * 64 + r] = kv.x;
            Kt[(c4v + 1) * 64 + r] = kv.y;
            Kt[(c4v + 2) * 64 + r] = kv.z;
            Kt[(c4v + 3) * 64 + r] = kv.w;
            *(float4*)(Vs + r * 128 + c4v) = *(const float4*)(Vgt + r * HD_ + c4v);
        }
        __syncthreads();

        float sreg[4][4];
        #pragma unroll
        for (int ii = 0; ii < 4; ++ii)
            #pragma unroll
            for (int jj = 0; jj < 4; ++jj) sreg[ii][jj] = 0.0f;

        #pragma unroll 4
        for (int kk = 0; kk < 128; ++kk) {
            float4 qv = *(const float4*)(Qt + kk * 64 + rg * 4);
            float4 kv = *(const float4*)(Kt + kk * 64 + cg * 4);
            sreg[0][0] += qv.x * kv.x; sreg[0][1] += qv.x * kv.y; sreg[0][2] += qv.x * kv.z; sreg[0][3] += qv.x * kv.w;
            sreg[1][0] += qv.y * kv.x; sreg[1][1] += qv.y * kv.y; sreg[1][2] += qv.y * kv.z; sreg[1][3] += qv.y * kv.w;
            sreg[2][0] += qv.z * kv.x; sreg[2][1] += qv.z * kv.y; sreg[2][2] += qv.z * kv.z; sreg[2][3] += qv.z * kv.w;
            sreg[3][0] += qv.w * kv.x; sreg[3][1] += qv.w * kv.y; sreg[3][2] += qv.w * kv.z; sreg[3][3] += qv.w * kv.w;
        }

        if (kt == qtile) {
            #pragma unroll
            for (int ii = 0; ii < 4; ++ii)
                #pragma unroll
                for (int jj = 0; jj < 4; ++jj)
                    if (cg * 4 + jj > rg * 4 + ii) sreg[ii][jj] = -1e30f;
        }

        #pragma unroll
        for (int ii = 0; ii < 4; ++ii) {
            float mx = fmaxf(fmaxf(sreg[ii][0], sreg[ii][1]), fmaxf(sreg[ii][2], sreg[ii][3]));
            #pragma unroll
            for (int offb = 1; offb < 16; offb <<= 1)
                mx = fmaxf(mx, __shfl_xor_sync(0xffffffffu, mx, offb));
            const float mnew = fmaxf(m_i[ii], mx);
            const float corr = __expf(m_i[ii] - mnew);
            m_i[ii] = mnew;
            float rs = 0.0f;
            #pragma unroll
            for (int jj = 0; jj < 4; ++jj) {
                const float p = __expf(sreg[ii][jj] - mnew);
                sreg[ii][jj] = p;
                rs += p;
            }
            #pragma unroll
            for (int offb = 1; offb < 16; offb <<= 1)
                rs += __shfl_xor_sync(0xffffffffu, rs, offb);
            l_i[ii] = l_i[ii] * corr + rs;
            #pragma unroll
            for (int hh = 0; hh < 8; ++hh) o[ii][hh] *= corr;
            *(float4*)(Ps + (rg * 4 + ii) * 68 + cg * 4) =
                make_float4(sreg[ii][0], sreg[ii][1], sreg[ii][2], sreg[ii][3]);
        }
        __syncthreads();

        #pragma unroll 2
        for (int j = 0; j < 64; ++j) {
            float4 v0 = *(const float4*)(Vs + j * 128 + cg * 8);
            float4 v1 = *(const float4*)(Vs + j * 128 + cg * 8 + 4);
            #pragma unroll
            for (int ii = 0; ii < 4; ++ii) {
                const float p = Ps[(rg * 4 + ii) * 68 + j];
                o[ii][0] += p * v0.x; o[ii][1] += p * v0.y;
                o[ii][2] += p * v0.z; o[ii][3] += p * v0.w;
                o[ii][4] += p * v1.x; o[ii][5] += p * v1.y;
                o[ii][6] += p * v1.z; o[ii][7] += p * v1.w;
            }
        }
    }

    #pragma unroll
    for (int ii = 0; ii < 4; ++ii) {
        const int r = rg * 4 + ii;
        const float inv = 1.0f / l_i[ii];
        float* op = Out + ((size_t)b * T_ + q0 + r) * D_ + h * HD_ + cg * 8;
        *(float4*)op = make_float4(o[ii][0] * inv, o[ii][1] * inv,
                                   o[ii][2] * inv, o[ii][3] * inv);
        *(float4*)(op + 4) = make_float4(o[ii][4] * inv, o[ii][5] * inv,
                                         o[ii][6] * inv, o[ii][7] * inv);
    }
}

// ---------------------------------------------------------------------------
// Launch
// ---------------------------------------------------------------------------
extern "C" void kernel_launch(void* const* d_in, const int* in_sizes, int n_in,
                              void* d_out, int out_size)
{
    const float* x  = (const float*)d_in[0];
    const float* wn = (const float*)d_in[2];
    const float* wq = (const float*)d_in[3];
    const float* wk = (const float*)d_in[4];
    const float* wv = (const float*)d_in[5];
    const float* wo = (const float*)d_in[6];
    float* out = (float*)d_out;

    float* base = nullptr;
    cudaGetSymbolAddress((void**)&base, g_scratch);
    float* xn = base;
    float* qb = base + 1ull * BTD_;
    float* kb = base + 2ull * BTD_;
    float* vb = base + 3ull * BTD_;
    float* ao = base + 4ull * BTD_;

    cudaFuncSetAttribute(gemm_mma, cudaFuncAttributeMaxDynamicSharedMemorySize,
                         GEMM_SMEM_BYTES);
    cudaFuncSetAttribute(attn_kernel, cudaFuncAttributeMaxDynamicSharedMemorySize,
                         ATT_SMEM_BYTES);

    rmsnorm_kernel<<<BT_, 256>>>(x, wn, xn);

    dim3 gg(D_ / 128, BT_ / 128);   // (16, 32)
    gemm_mma<<<gg, 256, GEMM_SMEM_BYTES>>>(xn, wq, qb, 0);
    gemm_mma<<<gg, 256, GEMM_SMEM_BYTES>>>(xn, wk, kb, 0);
    gemm_mma<<<gg, 256, GEMM_SMEM_BYTES>>>(xn, wv, vb, 0);

    attn_kernel<<<dim3(T_ / 64, B_ * H_), 256, ATT_SMEM_BYTES>>>(qb, kb, vb, ao);

    gemm_mma<<<gg, 256, GEMM_SMEM_BYTES>>>(ao, wo, out, 1);
}

// round 4
// speedup vs baseline: 4.0298x; 2.1283x over previous
#include <cuda_runtime.h>
#include <math.h>
#include <stdint.h>

#define B_ 2
#define T_ 2048
#define D_ 2048
#define H_ 16
#define HD_ 128
#define BT_ (B_ * T_)
#define BTD_ (B_ * T_ * D_)

// Scratch: xn, q, k, v, attn_out  (5 x 32MB = 160MB)
__device__ float g_scratch[5ull * BTD_];

// ---------------------------------------------------------------------------
// helpers
// ---------------------------------------------------------------------------
__device__ __forceinline__ uint32_t smem_u32(const void* p) {
    uint32_t a;
    asm("{ .reg .u64 t; cvta.to.shared.u64 t, %1; cvt.u32.u64 %0, t; }"
        : "=r"(a) : "l"(p));
    return a;
}

__device__ __forceinline__ void cp16(uint32_t s, const void* g) {
    asm volatile("cp.async.cg.shared.global [%0], [%1], 16;"
                 :: "r"(s), "l"(g) : "memory");
}

__device__ __forceinline__ uint32_t cvt_tf32(float x) {
    uint32_t r;
    asm("cvt.rna.tf32.f32 %0, %1;" : "=r"(r) : "f"(x));
    return r;
}

__device__ __forceinline__ float tf32f(float x) {
    return __uint_as_float(cvt_tf32(x));
}

__device__ __forceinline__ void mma_tf32(float* c, const uint32_t* a, const uint32_t* b) {
    asm volatile(
        "mma.sync.aligned.m16n8k8.row.col.f32.tf32.tf32.f32 "
        "{%0,%1,%2,%3}, {%4,%5,%6,%7}, {%8,%9}, {%0,%1,%2,%3};"
        : "+f"(c[0]), "+f"(c[1]), "+f"(c[2]), "+f"(c[3])
        : "r"(a[0]), "r"(a[1]), "r"(a[2]), "r"(a[3]), "r"(b[0]), "r"(b[1]));
}

// ---------------------------------------------------------------------------
// RMSNorm: one block per row of D=2048
// ---------------------------------------------------------------------------
__global__ void __launch_bounds__(256) rmsnorm_kernel(
    const float* __restrict__ x, const float* __restrict__ w, float* __restrict__ out)
{
    const int row = blockIdx.x;
    const float4* xr = (const float4*)(x + (size_t)row * D_);
    float4* orow = (float4*)(out + (size_t)row * D_);
    const float4* w4 = (const float4*)w;
    const int tid = threadIdx.x;

    float4 v0 = xr[tid];
    float4 v1 = xr[tid + 256];
    float ss = v0.x*v0.x + v0.y*v0.y + v0.z*v0.z + v0.w*v0.w
             + v1.x*v1.x + v1.y*v1.y + v1.z*v1.z + v1.w*v1.w;

    #pragma unroll
    for (int m = 16; m > 0; m >>= 1) ss += __shfl_xor_sync(0xffffffffu, ss, m);

    __shared__ float red[8];
    if ((tid & 31) == 0) red[tid >> 5] = ss;
    __syncthreads();
    float tot = red[0] + red[1] + red[2] + red[3] + red[4] + red[5] + red[6] + red[7];

    const float inv = 1.0f / (sqrtf(tot) * 0.022097086912079612f + 1e-8f);

    float4 w0 = w4[tid], w1 = w4[tid + 256];
    float4 o0, o1;
    o0.x = v0.x * w0.x * inv; o0.y = v0.y * w0.y * inv;
    o0.z = v0.z * w0.z * inv; o0.w = v0.w * w0.w * inv;
    o1.x = v1.x * w1.x * inv; o1.y = v1.y * w1.y * inv;
    o1.z = v1.z * w1.z * inv; o1.w = v1.w * w1.w * inv;
    orow[tid] = o0;
    orow[tid + 256] = o1;
}

// ---------------------------------------------------------------------------
// tf32 mma.sync GEMM: C = A @ W^T
// mode 0: qkv [B,H,T,HD] store, tf32-pre-rounded; mode 1: row-major fp32.
// ---------------------------------------------------------------------------
#define BK 32
#define LDW 36
#define STAGE_FLOATS (128 * LDW)
#define GEMM_SMEM_BYTES (4 * STAGE_FLOATS * 4)
#define NKT 64

__global__ void __launch_bounds__(256, 2) gemm_mma(
    const float* __restrict__ A, const float* __restrict__ W,
    float* __restrict__ C, int mode)
{
    extern __shared__ float sm[];
    float* As = sm;
    float* Bs = sm + 2 * STAGE_FLOATS;

    const int tid = threadIdx.x;
    const int lane = tid & 31;
    const int wid = tid >> 5;
    const int wm = (wid & 1) * 64;
    const int wn = (wid >> 1) * 32;
    const int bm = blockIdx.y, bn = blockIdx.x;

    const int r0 = tid >> 3;
    const int c4 = tid & 7;
    const float* Ag = A + (size_t)(bm * 128 + r0) * 2048 + c4 * 4;
    const float* Wg = W + (size_t)(bn * 128 + r0) * 2048 + c4 * 4;
    const uint32_t sA = smem_u32(As);
    const uint32_t sB = smem_u32(Bs);
    uint32_t soff[4];
    #pragma unroll
    for (int i = 0; i < 4; ++i)
        soff[i] = ((uint32_t)(r0 + 32 * i) * LDW + c4 * 4) * 4;

    float acc[4][4][4];
    #pragma unroll
    for (int mt = 0; mt < 4; ++mt)
        #pragma unroll
        for (int nt = 0; nt < 4; ++nt)
            #pragma unroll
            for (int q = 0; q < 4; ++q) acc[mt][nt][q] = 0.0f;

    {
        #pragma unroll
        for (int i = 0; i < 4; ++i) cp16(sA + soff[i], Ag + (size_t)(32 * i) * 2048);
        #pragma unroll
        for (int i = 0; i < 4; ++i) cp16(sB + soff[i], Wg + (size_t)(32 * i) * 2048);
        asm volatile("cp.async.commit_group;" ::: "memory");
    }

    for (int kt = 0; kt < NKT; ++kt) {
        const int s = kt & 1;
        if (kt + 1 < NKT) {
            const int s1 = (kt + 1) & 1;
            const uint32_t a1 = sA + s1 * STAGE_FLOATS * 4;
            const uint32_t b1 = sB + s1 * STAGE_FLOATS * 4;
            const float* ag = Ag + (kt + 1) * 32;
            const float* wg = Wg + (kt + 1) * 32;
            #pragma unroll
            for (int i = 0; i < 4; ++i) cp16(a1 + soff[i], ag + (size_t)(32 * i) * 2048);
            #pragma unroll
            for (int i = 0; i < 4; ++i) cp16(b1 + soff[i], wg + (size_t)(32 * i) * 2048);
            asm volatile("cp.async.commit_group;" ::: "memory");
            asm volatile("cp.async.wait_group 1;" ::: "memory");
        } else {
            asm volatile("cp.async.wait_group 0;" ::: "memory");
        }
        __syncthreads();

        const float* Ast = As + s * STAGE_FLOATS;
        const float* Bst = Bs + s * STAGE_FLOATS;
        #pragma unroll
        for (int kk = 0; kk < 4; ++kk) {
            const int k = kk * 8;
            uint32_t a[4][4], b[4][2];
            #pragma unroll
            for (int mt = 0; mt < 4; ++mt) {
                const float* ap = Ast + (wm + mt * 16 + (lane >> 2)) * LDW + k + (lane & 3);
                a[mt][0] = cvt_tf32(ap[0]);
                a[mt][1] = cvt_tf32(ap[8 * LDW]);
                a[mt][2] = cvt_tf32(ap[4]);
                a[mt][3] = cvt_tf32(ap[8 * LDW + 4]);
            }
            #pragma unroll
            for (int nt = 0; nt < 4; ++nt) {
                const float* bp = Bst + (wn + nt * 8 + (lane >> 2)) * LDW + k + (lane & 3);
                b[nt][0] = cvt_tf32(bp[0]);
                b[nt][1] = cvt_tf32(bp[4]);
            }
            #pragma unroll
            for (int mt = 0; mt < 4; ++mt)
                #pragma unroll
                for (int nt = 0; nt < 4; ++nt)
                    mma_tf32(acc[mt][nt], a[mt], b[nt]);
        }
        __syncthreads();
    }

    const int rbase = bm * 128 + wm + (lane >> 2);
    const int cbase = wn + (lane & 3) * 2;
    #pragma unroll
    for (int mt = 0; mt < 4; ++mt) {
        #pragma unroll
        for (int half = 0; half < 2; ++half) {
            const int row = rbase + mt * 16 + half * 8;
            if (mode == 0) {
                const int b = row >> 11;
                const int t = row & (T_ - 1);
                float* cp = C + (((size_t)(b * H_ + bn)) * T_ + t) * HD_ + cbase;
                #pragma unroll
                for (int nt = 0; nt < 4; ++nt)
                    *(float2*)(cp + nt * 8) =
                        make_float2(tf32f(acc[mt][nt][half * 2]),
                                    tf32f(acc[mt][nt][half * 2 + 1]));
            } else {
                float* cp = C + (size_t)row * D_ + bn * 128 + cbase;
                #pragma unroll
                for (int nt = 0; nt < 4; ++nt)
                    *(float2*)(cp + nt * 8) =
                        make_float2(acc[mt][nt][half * 2], acc[mt][nt][half * 2 + 1]);
            }
        }
    }
}

// ---------------------------------------------------------------------------
// Tensor-core flash attention (tf32 mma.sync, causal).
// CTA: 128 q-rows; kv step 64; 8 warps (4 M x 2 N).
// Q/K/V are pre-rounded to tf32 by gemm mode 0.
// ---------------------------------------------------------------------------
#define LDQ 132
#define LDK 132
#define LDV 136
#define LDP 68
#define QS_OFF 0
#define KS_OFF 16896                 // Qs: 128*132
#define KS_STAGE 8448                // 64*132
#define VS_OFF (KS_OFF + 2 * KS_STAGE)
#define PS_OFF (VS_OFF + 64 * LDV)   // Vs: 64*136 = 8704
#define MR_OFF (PS_OFF + 128 * LDP)  // Ps: 128*68 = 8704
#define LR_OFF (MR_OFF + 256)
#define ATT_SMEM_FLOATS (LR_OFF + 256)
#define ATT_SMEM_BYTES (ATT_SMEM_FLOATS * 4)   // 206848
#define ATT_SCALE 0.08838834764831845f

__global__ void __launch_bounds__(256, 1) attn_mma(
    const float* __restrict__ Q, const float* __restrict__ K,
    const float* __restrict__ V, float* __restrict__ Out)
{
    extern __shared__ float sm[];
    float* Qs = sm + QS_OFF;
    float* Ks = sm + KS_OFF;
    float* Vs = sm + VS_OFF;
    float* Ps = sm + PS_OFF;
    float* mred = sm + MR_OFF;       // [2][128]
    float* lred = sm + LR_OFF;       // [2][128]

    const int qt = (int)gridDim.x - 1 - (int)blockIdx.x;  // heavy tiles first
    const int bh = blockIdx.y;
    const int bz = bh >> 4;
    const int head = bh & (H_ - 1);
    const int q0 = qt * 128;
    const int tid = threadIdx.x;
    const int lane = tid & 31;
    const int wid = tid >> 5;
    const int wm = (wid & 3) * 32;       // rows (S and O)
    const int wn = (wid >> 2) * 32;      // S kv-col group
    const int wno = (wid >> 2) * 64;     // O hd-col group
    const int wnid = wid >> 2;
    const int lr4 = lane >> 2;           // 0..7
    const int lc4 = lane & 3;            // 0..3

    const float* Qg = Q + ((size_t)bh * T_ + q0) * HD_;
    const float* Kg = K + (size_t)bh * T_ * HD_;
    const float* Vg = V + (size_t)bh * T_ * HD_;

    // ---- fill Q smem (scaled + tf32-rounded) ----
    #pragma unroll
    for (int j = 0; j < 16; ++j) {
        const int i = tid + j * 256;      // float4 chunk 0..4095
        const int r = i >> 5;
        const int c = (i & 31) << 2;
        float4 v = *(const float4*)(Qg + r * HD_ + c);
        float* d = Qs + r * LDQ + c;
        d[0] = tf32f(v.x * ATT_SCALE);
        d[1] = tf32f(v.y * ATT_SCALE);
        d[2] = tf32f(v.z * ATT_SCALE);
        d[3] = tf32f(v.w * ATT_SCALE);
    }

    // per-thread tile-load geometry (64 rows x 128 cols, float4 chunks)
    int ldr[8], ldc[8];
    #pragma unroll
    for (int j = 0; j < 8; ++j) {
        const int i = tid + j * 256;
        ldr[j] = i >> 5;
        ldc[j] = (i & 31) << 2;
    }
    const uint32_t sKs = smem_u32(Ks);
    const uint32_t sVs = smem_u32(Vs);

    const int ntiles = 2 * (qt + 1);

    // prologue: K(0)
    #pragma unroll
    for (int j = 0; j < 8; ++j)
        cp16(sKs + (uint32_t)(ldr[j] * LDK + ldc[j]) * 4, Kg + (size_t)ldr[j] * HD_ + ldc[j]);
    asm volatile("cp.async.commit_group;" ::: "memory");

    float m_i[4], l_i[4];
    float oacc[2][8][4];
    #pragma unroll
    for (int r = 0; r < 4; ++r) { m_i[r] = -INFINITY; l_i[r] = 0.0f; }
    #pragma unroll
    for (int mt = 0; mt < 2; ++mt)
        #pragma unroll
        for (int nt = 0; nt < 8; ++nt)
            #pragma unroll
            for (int q = 0; q < 4; ++q) oacc[mt][nt][q] = 0.0f;

    for (int t = 0; t < ntiles; ++t) {
        const int kv0 = t * 64;
        const int st = t & 1;

        // 1. K(t) ready
        asm volatile("cp.async.wait_group 0;" ::: "memory");
        __syncthreads();

        // 2. launch V(t)
        {
            const float* vg = Vg + (size_t)kv0 * HD_;
            #pragma unroll
            for (int j = 0; j < 8; ++j)
                cp16(sVs + (uint32_t)(ldr[j] * LDV + ldc[j]) * 4, vg + (size_t)ldr[j] * HD_ + ldc[j]);
            asm volatile("cp.async.commit_group;" ::: "memory");
        }

        // 3. S = Q @ K^T
        float sacc[2][4][4];
        #pragma unroll
        for (int mt = 0; mt < 2; ++mt)
            #pragma unroll
            for (int nt = 0; nt < 4; ++nt)
                #pragma unroll
                for (int q = 0; q < 4; ++q) sacc[mt][nt][q] = 0.0f;

        const float* Kst = Ks + st * KS_STAGE;
        #pragma unroll
        for (int kk = 0; kk < 16; ++kk) {
            const int k0 = kk * 8;
            uint32_t a[2][4], b[4][2];
            #pragma unroll
            for (int mt = 0; mt < 2; ++mt) {
                const float* ap = Qs + (wm + mt * 16 + lr4) * LDQ + k0 + lc4;
                a[mt][0] = __float_as_uint(ap[0]);
                a[mt][1] = __float_as_uint(ap[8 * LDQ]);
                a[mt][2] = __float_as_uint(ap[4]);
                a[mt][3] = __float_as_uint(ap[8 * LDQ + 4]);
            }
            #pragma unroll
            for (int nt = 0; nt < 4; ++nt) {
                const float* bp = Kst + (wn + nt * 8 + lr4) * LDK + k0 + lc4;
                b[nt][0] = __float_as_uint(bp[0]);
                b[nt][1] = __float_as_uint(bp[4]);
            }
            #pragma unroll
            for (int mt = 0; mt < 2; ++mt)
                #pragma unroll
                for (int nt = 0; nt < 4; ++nt)
                    mma_tf32(sacc[mt][nt], a[mt], b[nt]);
        }

        // 4. prefetch K(t+1) into other stage
        const bool havek = (t + 1 < ntiles);
        if (havek) {
            const float* kg = Kg + (size_t)(kv0 + 64) * HD_;
            const uint32_t kb = sKs + (uint32_t)((st ^ 1) * KS_STAGE) * 4;
            #pragma unroll
            for (int j = 0; j < 8; ++j)
                cp16(kb + (uint32_t)(ldr[j] * LDK + ldc[j]) * 4, kg + (size_t)ldr[j] * HD_ + ldc[j]);
            asm volatile("cp.async.commit_group;" ::: "memory");
        }

        // causal mask (only diagonal-region tiles)
        if (t >= 2 * qt) {
            #pragma unroll
            for (int mt = 0; mt < 2; ++mt)
                #pragma unroll
                for (int nt = 0; nt < 4; ++nt)
                    #pragma unroll
                    for (int q = 0; q < 4; ++q) {
                        const int row = q0 + wm + mt * 16 + (q >> 1) * 8 + lr4;
                        const int col = kv0 + wn + nt * 8 + lc4 * 2 + (q & 1);
                        if (col > row) sacc[mt][nt][q] = -1e30f;
                    }
        }

        // 5. row max: quad reduce + cross-warp via smem
        float pmax[4];
        #pragma unroll
        for (int r = 0; r < 4; ++r) pmax[r] = -INFINITY;
        #pragma unroll
        for (int mt = 0; mt < 2; ++mt)
            #pragma unroll
            for (int nt = 0; nt < 4; ++nt)
                #pragma unroll
                for (int q = 0; q < 4; ++q)
                    pmax[mt * 2 + (q >> 1)] = fmaxf(pmax[mt * 2 + (q >> 1)], sacc[mt][nt][q]);
        #pragma unroll
        for (int r = 0; r < 4; ++r) {
            pmax[r] = fmaxf(pmax[r], __shfl_xor_sync(0xffffffffu, pmax[r], 1));
            pmax[r] = fmaxf(pmax[r], __shfl_xor_sync(0xffffffffu, pmax[r], 2));
        }
        if (lc4 == 0) {
            #pragma unroll
            for (int r = 0; r < 4; ++r) {
                const int rl = wm + (r >> 1) * 16 + (r & 1) * 8 + lr4;
                mred[wnid * 128 + rl] = pmax[r];
            }
        }
        __syncthreads();

        // 6. exp, rescale O, write P (tf32), partial sums
        float corr[4], psum[4];
        #pragma unroll
        for (int r = 0; r < 4; ++r) {
            const int rl = wm + (r >> 1) * 16 + (r & 1) * 8 + lr4;
            const float mnew = fmaxf(m_i[r], fmaxf(mred[rl], mred[128 + rl]));
            corr[r] = __expf(m_i[r] - mnew);
            m_i[r] = mnew;
            psum[r] = 0.0f;
        }
        #pragma unroll
        for (int mt = 0; mt < 2; ++mt)
            #pragma unroll
            for (int nt = 0; nt < 4; ++nt)
                #pragma unroll
                for (int h = 0; h < 2; ++h) {
                    const int r = mt * 2 + h;
                    const float p0 = __expf(sacc[mt][nt][h * 2]     - m_i[r]);
                    const float p1 = __expf(sacc[mt][nt][h * 2 + 1] - m_i[r]);
                    psum[r] += p0 + p1;
                    const int rl = wm + mt * 16 + h * 8 + lr4;
                    *(float2*)(Ps + rl * LDP + wn + nt * 8 + lc4 * 2) =
                        make_float2(tf32f(p0), tf32f(p1));
                }
        #pragma unroll
        for (int r = 0; r < 4; ++r) {
            psum[r] += __shfl_xor_sync(0xffffffffu, psum[r], 1);
            psum[r] += __shfl_xor_sync(0xffffffffu, psum[r], 2);
        }
        if (lc4 == 0) {
            #pragma unroll
            for (int r = 0; r < 4; ++r) {
                const int rl = wm + (r >> 1) * 16 + (r & 1) * 8 + lr4;
                lred[wnid * 128 + rl] = psum[r];
            }
        }
        #pragma unroll
        for (int mt = 0; mt < 2; ++mt)
            #pragma unroll
            for (int nt = 0; nt < 8; ++nt)
                #pragma unroll
                for (int q = 0; q < 4; ++q)
                    oacc[mt][nt][q] *= corr[mt * 2 + (q >> 1)];

        // 7. wait V(t) (K(t+1) may stay in flight)
        if (havek) asm volatile("cp.async.wait_group 1;" ::: "memory");
        else       asm volatile("cp.async.wait_group 0;" ::: "memory");
        // 8.
        __syncthreads();

        // 9. finalize l
        #pragma unroll
        for (int r = 0; r < 4; ++r) {
            const int rl = wm + (r >> 1) * 16 + (r & 1) * 8 + lr4;
            l_i[r] = l_i[r] * corr[r] + lred[rl] + lred[128 + rl];
        }

        // 10. O += P @ V
        #pragma unroll
        for (int kk = 0; kk < 8; ++kk) {
            const int k0 = kk * 8;
            uint32_t a[2][4], b[8][2];
            #pragma unroll
            for (int mt = 0; mt < 2; ++mt) {
                const float* ap = Ps + (wm + mt * 16 + lr4) * LDP + k0 + lc4;
                a[mt][0] = __float_as_uint(ap[0]);
                a[mt][1] = __float_as_uint(ap[8 * LDP]);
                a[mt][2] = __float_as_uint(ap[4]);
                a[mt][3] = __float_as_uint(ap[8 * LDP + 4]);
            }
            #pragma unroll
            for (int nt = 0; nt < 8; ++nt) {
                const float* bp = Vs + (k0 + lc4) * LDV + wno + nt * 8 + lr4;
                b[nt][0] = __float_as_uint(bp[0]);
                b[nt][1] = __float_as_uint(bp[4 * LDV]);
            }
            #pragma unroll
            for (int mt = 0; mt < 2; ++mt)
                #pragma unroll
                for (int nt = 0; nt < 8; ++nt)
                    mma_tf32(oacc[mt][nt], a[mt], b[nt]);
        }
    }

    // epilogue: normalize and store [b, t, head*HD + col]
    #pragma unroll
    for (int mt = 0; mt < 2; ++mt)
        #pragma unroll
        for (int h = 0; h < 2; ++h) {
            const int r = mt * 2 + h;
            const int row = q0 + wm + mt * 16 + h * 8 + lr4;
            const float inv = 1.0f / l_i[r];
            float* op = Out + ((size_t)bz * T_ + row) * D_ + head * HD_ + wno + lc4 * 2;
            #pragma unroll
            for (int nt = 0; nt < 8; ++nt)
                *(float2*)(op + nt * 8) =
                    make_float2(oacc[mt][nt][h * 2] * inv, oacc[mt][nt][h * 2 + 1] * inv);
        }
}

// ---------------------------------------------------------------------------
// Launch
// ---------------------------------------------------------------------------
extern "C" void kernel_launch(void* const* d_in, const int* in_sizes, int n_in,
                              void* d_out, int out_size)
{
    const float* x  = (const float*)d_in[0];
    const float* wn = (const float*)d_in[2];
    const float* wq = (const float*)d_in[3];
    const float* wk = (const float*)d_in[4];
    const float* wv = (const float*)d_in[5];
    const float* wo = (const float*)d_in[6];
    float* out = (float*)d_out;

    float* base = nullptr;
    cudaGetSymbolAddress((void**)&base, g_scratch);
    float* xn = base;
    float* qb = base + 1ull * BTD_;
    float* kb = base + 2ull * BTD_;
    float* vb = base + 3ull * BTD_;
    float* ao = base + 4ull * BTD_;

    cudaFuncSetAttribute(gemm_mma, cudaFuncAttributeMaxDynamicSharedMemorySize,
                         GEMM_SMEM_BYTES);
    cudaFuncSetAttribute(attn_mma, cudaFuncAttributeMaxDynamicSharedMemorySize,
                         ATT_SMEM_BYTES);

    rmsnorm_kernel<<<BT_, 256>>>(x, wn, xn);

    dim3 gg(D_ / 128, BT_ / 128);   // (16, 32)
    gemm_mma<<<gg, 256, GEMM_SMEM_BYTES>>>(xn, wq, qb, 0);
    gemm_mma<<<gg, 256, GEMM_SMEM_BYTES>>>(xn, wk, kb, 0);
    gemm_mma<<<gg, 256, GEMM_SMEM_BYTES>>>(xn, wv, vb, 0);

    attn_mma<<<dim3(T_ / 128, B_ * H_), 256, ATT_SMEM_BYTES>>>(qb, kb, vb, ao);

    gemm_mma<<<gg, 256, GEMM_SMEM_BYTES>>>(ao, wo, out, 1);
}

// round 5
// speedup vs baseline: 4.3804x; 1.0870x over previous
#include <cuda_runtime.h>
#include <math.h>
#include <stdint.h>

#define B_ 2
#define T_ 2048
#define D_ 2048
#define H_ 16
#define HD_ 128
#define BT_ (B_ * T_)
#define BTD_ (B_ * T_ * D_)
#define DD_ (D_ * D_)

// Scratch: xn, q, k, v, attn_out (5 x 33.5MB) + 4 tf32-rounded weights (4 x 16.8MB)
__device__ float g_scratch[5ull * BTD_ + 4ull * DD_];

// ---------------------------------------------------------------------------
// helpers
// ---------------------------------------------------------------------------
__device__ __forceinline__ uint32_t smem_u32(const void* p) {
    uint32_t a;
    asm("{ .reg .u64 t; cvta.to.shared.u64 t, %1; cvt.u32.u64 %0, t; }"
        : "=r"(a) : "l"(p));
    return a;
}

__device__ __forceinline__ void cp16(uint32_t s, const void* g) {
    asm volatile("cp.async.cg.shared.global [%0], [%1], 16;"
                 :: "r"(s), "l"(g) : "memory");
}

__device__ __forceinline__ uint32_t cvt_tf32(float x) {
    uint32_t r;
    asm("cvt.rna.tf32.f32 %0, %1;" : "=r"(r) : "f"(x));
    return r;
}

__device__ __forceinline__ float tf32f(float x) {
    return __uint_as_float(cvt_tf32(x));
}

__device__ __forceinline__ void mma_tf32(float* c, const uint32_t* a, const uint32_t* b) {
    asm volatile(
        "mma.sync.aligned.m16n8k8.row.col.f32.tf32.tf32.f32 "
        "{%0,%1,%2,%3}, {%4,%5,%6,%7}, {%8,%9}, {%0,%1,%2,%3};"
        : "+f"(c[0]), "+f"(c[1]), "+f"(c[2]), "+f"(c[3])
        : "r"(a[0]), "r"(a[1]), "r"(a[2]), "r"(a[3]), "r"(b[0]), "r"(b[1]));
}

// ---------------------------------------------------------------------------
// tf32 pre-rounding of a weight matrix (float4 elementwise)
// ---------------------------------------------------------------------------
__global__ void __launch_bounds__(256) round_tf32_kernel(
    const float4* __restrict__ src, float4* __restrict__ dst)
{
    const int i = blockIdx.x * 256 + threadIdx.x;
    float4 v = src[i];
    v.x = tf32f(v.x); v.y = tf32f(v.y); v.z = tf32f(v.z); v.w = tf32f(v.w);
    dst[i] = v;
}

// ---------------------------------------------------------------------------
// RMSNorm: one block per row of D=2048; output tf32-rounded
// ---------------------------------------------------------------------------
__global__ void __launch_bounds__(256) rmsnorm_kernel(
    const float* __restrict__ x, const float* __restrict__ w, float* __restrict__ out)
{
    const int row = blockIdx.x;
    const float4* xr = (const float4*)(x + (size_t)row * D_);
    float4* orow = (float4*)(out + (size_t)row * D_);
    const float4* w4 = (const float4*)w;
    const int tid = threadIdx.x;

    float4 v0 = xr[tid];
    float4 v1 = xr[tid + 256];
    float ss = v0.x*v0.x + v0.y*v0.y + v0.z*v0.z + v0.w*v0.w
             + v1.x*v1.x + v1.y*v1.y + v1.z*v1.z + v1.w*v1.w;

    #pragma unroll
    for (int m = 16; m > 0; m >>= 1) ss += __shfl_xor_sync(0xffffffffu, ss, m);

    __shared__ float red[8];
    if ((tid & 31) == 0) red[tid >> 5] = ss;
    __syncthreads();
    float tot = red[0] + red[1] + red[2] + red[3] + red[4] + red[5] + red[6] + red[7];

    const float inv = 1.0f / (sqrtf(tot) * 0.022097086912079612f + 1e-8f);

    float4 w0 = w4[tid], w1 = w4[tid + 256];
    float4 o0, o1;
    o0.x = tf32f(v0.x * w0.x * inv); o0.y = tf32f(v0.y * w0.y * inv);
    o0.z = tf32f(v0.z * w0.z * inv); o0.w = tf32f(v0.w * w0.w * inv);
    o1.x = tf32f(v1.x * w1.x * inv); o1.y = tf32f(v1.y * w1.y * inv);
    o1.z = tf32f(v1.z * w1.z * inv); o1.w = tf32f(v1.w * w1.w * inv);
    orow[tid] = o0;
    orow[tid + 256] = o1;
}

// ---------------------------------------------------------------------------
// tf32 mma.sync GEMM core (inputs pre-rounded to tf32; no in-loop CVT)
// 128x128x32 CTA tile, 8 warps (2x4), warp tile 64x32 = 4x4 m16n8k8.
// ---------------------------------------------------------------------------
#define BK 32
#define LDW 36
#define STAGE_FLOATS (128 * LDW)
#define GEMM_SMEM_BYTES (4 * STAGE_FLOATS * 4)
#define NKT 64

struct GemmAcc { float acc[4][4][4]; };

__device__ __forceinline__ void gemm_core(
    const float* __restrict__ A, const float* __restrict__ W,
    int bm, int bn, float* sm, GemmAcc& g)
{
    float* As = sm;
    float* Bs = sm + 2 * STAGE_FLOATS;

    const int tid = threadIdx.x;
    const int lane = tid & 31;
    const int wid = tid >> 5;
    const int wm = (wid & 1) * 64;
    const int wn = (wid >> 1) * 32;

    const int r0 = tid >> 3;
    const int c4 = tid & 7;
    const float* Ag = A + (size_t)(bm * 128 + r0) * 2048 + c4 * 4;
    const float* Wg = W + (size_t)(bn * 128 + r0) * 2048 + c4 * 4;
    const uint32_t sA = smem_u32(As);
    const uint32_t sB = smem_u32(Bs);
    uint32_t soff[4];
    #pragma unroll
    for (int i = 0; i < 4; ++i)
        soff[i] = ((uint32_t)(r0 + 32 * i) * LDW + c4 * 4) * 4;

    #pragma unroll
    for (int mt = 0; mt < 4; ++mt)
        #pragma unroll
        for (int nt = 0; nt < 4; ++nt)
            #pragma unroll
            for (int q = 0; q < 4; ++q) g.acc[mt][nt][q] = 0.0f;

    {
        #pragma unroll
        for (int i = 0; i < 4; ++i) cp16(sA + soff[i], Ag + (size_t)(32 * i) * 2048);
        #pragma unroll
        for (int i = 0; i < 4; ++i) cp16(sB + soff[i], Wg + (size_t)(32 * i) * 2048);
        asm volatile("cp.async.commit_group;" ::: "memory");
    }

    for (int kt = 0; kt < NKT; ++kt) {
        const int s = kt & 1;
        if (kt + 1 < NKT) {
            const int s1 = (kt + 1) & 1;
            const uint32_t a1 = sA + s1 * STAGE_FLOATS * 4;
            const uint32_t b1 = sB + s1 * STAGE_FLOATS * 4;
            const float* ag = Ag + (kt + 1) * 32;
            const float* wg = Wg + (kt + 1) * 32;
            #pragma unroll
            for (int i = 0; i < 4; ++i) cp16(a1 + soff[i], ag + (size_t)(32 * i) * 2048);
            #pragma unroll
            for (int i = 0; i < 4; ++i) cp16(b1 + soff[i], wg + (size_t)(32 * i) * 2048);
            asm volatile("cp.async.commit_group;" ::: "memory");
            asm volatile("cp.async.wait_group 1;" ::: "memory");
        } else {
            asm volatile("cp.async.wait_group 0;" ::: "memory");
        }
        __syncthreads();

        const float* Ast = As + s * STAGE_FLOATS;
        const float* Bst = Bs + s * STAGE_FLOATS;
        #pragma unroll
        for (int kk = 0; kk < 4; ++kk) {
            const int k = kk * 8;
            uint32_t a[4][4], b[4][2];
            #pragma unroll
            for (int mt = 0; mt < 4; ++mt) {
                const float* ap = Ast + (wm + mt * 16 + (lane >> 2)) * LDW + k + (lane & 3);
                a[mt][0] = __float_as_uint(ap[0]);
                a[mt][1] = __float_as_uint(ap[8 * LDW]);
                a[mt][2] = __float_as_uint(ap[4]);
                a[mt][3] = __float_as_uint(ap[8 * LDW + 4]);
            }
            #pragma unroll
            for (int nt = 0; nt < 4; ++nt) {
                const float* bp = Bst + (wn + nt * 8 + (lane >> 2)) * LDW + k + (lane & 3);
                b[nt][0] = __float_as_uint(bp[0]);
                b[nt][1] = __float_as_uint(bp[4]);
            }
            #pragma unroll
            for (int mt = 0; mt < 4; ++mt)
                #pragma unroll
                for (int nt = 0; nt < 4; ++nt)
                    mma_tf32(g.acc[mt][nt], a[mt], b[nt]);
        }
        __syncthreads();
    }
}

// Fused QKV: grid (48, 32); bn>>4 selects {wq,wk,wv} and q/k/v output buffer.
// Stores [B,H,T,HD] layout, tf32-rounded.
__global__ void __launch_bounds__(256, 2) gemm_qkv(
    const float* __restrict__ A, const float* __restrict__ Wq,
    const float* __restrict__ Wk, const float* __restrict__ Wv,
    float* __restrict__ QKV)
{
    extern __shared__ float sm[];
    const int bm = blockIdx.y;
    const int sel = blockIdx.x >> 4;
    const int bn = blockIdx.x & 15;
    const float* W = (sel == 0) ? Wq : (sel == 1) ? Wk : Wv;
    float* C = QKV + (size_t)sel * BTD_;

    GemmAcc g;
    gemm_core(A, W, bm, bn, sm, g);

    const int lane = threadIdx.x & 31;
    const int wid = threadIdx.x >> 5;
    const int wm = (wid & 1) * 64;
    const int wn = (wid >> 1) * 32;
    const int rbase = bm * 128 + wm + (lane >> 2);
    const int cbase = wn + (lane & 3) * 2;
    #pragma unroll
    for (int mt = 0; mt < 4; ++mt)
        #pragma unroll
        for (int half = 0; half < 2; ++half) {
            const int row = rbase + mt * 16 + half * 8;
            const int b = row >> 11;
            const int t = row & (T_ - 1);
            float* cp = C + (((size_t)(b * H_ + bn)) * T_ + t) * HD_ + cbase;
            #pragma unroll
            for (int nt = 0; nt < 4; ++nt)
                *(float2*)(cp + nt * 8) =
                    make_float2(tf32f(g.acc[mt][nt][half * 2]),
                                tf32f(g.acc[mt][nt][half * 2 + 1]));
        }
}

// Plain GEMM (final projection): row-major fp32 store.
__global__ void __launch_bounds__(256, 2) gemm_out(
    const float* __restrict__ A, const float* __restrict__ W, float* __restrict__ C)
{
    extern __shared__ float sm[];
    const int bm = blockIdx.y, bn = blockIdx.x;

    GemmAcc g;
    gemm_core(A, W, bm, bn, sm, g);

    const int lane = threadIdx.x & 31;
    const int wid = threadIdx.x >> 5;
    const int wm = (wid & 1) * 64;
    const int wn = (wid >> 1) * 32;
    const int rbase = bm * 128 + wm + (lane >> 2);
    const int cbase = wn + (lane & 3) * 2;
    #pragma unroll
    for (int mt = 0; mt < 4; ++mt)
        #pragma unroll
        for (int half = 0; half < 2; ++half) {
            const int row = rbase + mt * 16 + half * 8;
            float* cp = C + (size_t)row * D_ + bn * 128 + cbase;
            #pragma unroll
            for (int nt = 0; nt < 4; ++nt)
                *(float2*)(cp + nt * 8) =
                    make_float2(g.acc[mt][nt][half * 2], g.acc[mt][nt][half * 2 + 1]);
        }
}

// ---------------------------------------------------------------------------
// Tensor-core flash attention (tf32 mma.sync, causal).
// CTA: 128 q-rows; kv step 64; 8 warps (4 M x 2 N). Inputs pre-rounded tf32.
// ---------------------------------------------------------------------------
#define LDQ 132
#define LDK 132
#define LDV 136
#define LDP 68
#define QS_OFF 0
#define KS_OFF 16896                 // Qs: 128*132
#define KS_STAGE 8448                // 64*132
#define VS_OFF (KS_OFF + 2 * KS_STAGE)
#define PS_OFF (VS_OFF + 64 * LDV)   // Vs: 64*136 = 8704
#define MR_OFF (PS_OFF + 128 * LDP)  // Ps: 128*68 = 8704
#define LR_OFF (MR_OFF + 256)
#define ATT_SMEM_FLOATS (LR_OFF + 256)
#define ATT_SMEM_BYTES (ATT_SMEM_FLOATS * 4)
#define ATT_SCALE 0.08838834764831845f

__global__ void __launch_bounds__(256, 1) attn_mma(
    const float* __restrict__ Q, const float* __restrict__ K,
    const float* __restrict__ V, float* __restrict__ Out)
{
    extern __shared__ float sm[];
    float* Qs = sm + QS_OFF;
    float* Ks = sm + KS_OFF;
    float* Vs = sm + VS_OFF;
    float* Ps = sm + PS_OFF;
    float* mred = sm + MR_OFF;
    float* lred = sm + LR_OFF;

    const int qt = (int)gridDim.x - 1 - (int)blockIdx.x;
    const int bh = blockIdx.y;
    const int bz = bh >> 4;
    const int head = bh & (H_ - 1);
    const int q0 = qt * 128;
    const int tid = threadIdx.x;
    const int lane = tid & 31;
    const int wid = tid >> 5;
    const int wm = (wid & 3) * 32;
    const int wn = (wid >> 2) * 32;
    const int wno = (wid >> 2) * 64;
    const int wnid = wid >> 2;
    const int lr4 = lane >> 2;
    const int lc4 = lane & 3;

    const float* Qg = Q + ((size_t)bh * T_ + q0) * HD_;
    const float* Kg = K + (size_t)bh * T_ * HD_;
    const float* Vg = V + (size_t)bh * T_ * HD_;

    #pragma unroll
    for (int j = 0; j < 16; ++j) {
        const int i = tid + j * 256;
        const int r = i >> 5;
        const int c = (i & 31) << 2;
        float4 v = *(const float4*)(Qg + r * HD_ + c);
        float* d = Qs + r * LDQ + c;
        d[0] = tf32f(v.x * ATT_SCALE);
        d[1] = tf32f(v.y * ATT_SCALE);
        d[2] = tf32f(v.z * ATT_SCALE);
        d[3] = tf32f(v.w * ATT_SCALE);
    }

    int ldr[8], ldc[8];
    #pragma unroll
    for (int j = 0; j < 8; ++j) {
        const int i = tid + j * 256;
        ldr[j] = i >> 5;
        ldc[j] = (i & 31) << 2;
    }
    const uint32_t sKs = smem_u32(Ks);
    const uint32_t sVs = smem_u32(Vs);

    const int ntiles = 2 * (qt + 1);

    #pragma unroll
    for (int j = 0; j < 8; ++j)
        cp16(sKs + (uint32_t)(ldr[j] * LDK + ldc[j]) * 4, Kg + (size_t)ldr[j] * HD_ + ldc[j]);
    asm volatile("cp.async.commit_group;" ::: "memory");

    float m_i[4], l_i[4];
    float oacc[2][8][4];
    #pragma unroll
    for (int r = 0; r < 4; ++r) { m_i[r] = -INFINITY; l_i[r] = 0.0f; }
    #pragma unroll
    for (int mt = 0; mt < 2; ++mt)
        #pragma unroll
        for (int nt = 0; nt < 8; ++nt)
            #pragma unroll
            for (int q = 0; q < 4; ++q) oacc[mt][nt][q] = 0.0f;

    for (int t = 0; t < ntiles; ++t) {
        const int kv0 = t * 64;
        const int st = t & 1;

        asm volatile("cp.async.wait_group 0;" ::: "memory");
        __syncthreads();

        {
            const float* vg = Vg + (size_t)kv0 * HD_;
            #pragma unroll
            for (int j = 0; j < 8; ++j)
                cp16(sVs + (uint32_t)(ldr[j] * LDV + ldc[j]) * 4, vg + (size_t)ldr[j] * HD_ + ldc[j]);
            asm volatile("cp.async.commit_group;" ::: "memory");
        }

        float sacc[2][4][4];
        #pragma unroll
        for (int mt = 0; mt < 2; ++mt)
            #pragma unroll
            for (int nt = 0; nt < 4; ++nt)
                #pragma unroll
                for (int q = 0; q < 4; ++q) sacc[mt][nt][q] = 0.0f;

        const float* Kst = Ks + st * KS_STAGE;
        #pragma unroll
        for (int kk = 0; kk < 16; ++kk) {
            const int k0 = kk * 8;
            uint32_t a[2][4], b[4][2];
            #pragma unroll
            for (int mt = 0; mt < 2; ++mt) {
                const float* ap = Qs + (wm + mt * 16 + lr4) * LDQ + k0 + lc4;
                a[mt][0] = __float_as_uint(ap[0]);
                a[mt][1] = __float_as_uint(ap[8 * LDQ]);
                a[mt][2] = __float_as_uint(ap[4]);
                a[mt][3] = __float_as_uint(ap[8 * LDQ + 4]);
            }
            #pragma unroll
            for (int nt = 0; nt < 4; ++nt) {
                const float* bp = Kst + (wn + nt * 8 + lr4) * LDK + k0 + lc4;
                b[nt][0] = __float_as_uint(bp[0]);
                b[nt][1] = __float_as_uint(bp[4]);
            }
            #pragma unroll
            for (int mt = 0; mt < 2; ++mt)
                #pragma unroll
                for (int nt = 0; nt < 4; ++nt)
                    mma_tf32(sacc[mt][nt], a[mt], b[nt]);
        }

        const bool havek = (t + 1 < ntiles);
        if (havek) {
            const float* kg = Kg + (size_t)(kv0 + 64) * HD_;
            const uint32_t kb = sKs + (uint32_t)((st ^ 1) * KS_STAGE) * 4;
            #pragma unroll
            for (int j = 0; j < 8; ++j)
                cp16(kb + (uint32_t)(ldr[j] * LDK + ldc[j]) * 4, kg + (size_t)ldr[j] * HD_ + ldc[j]);
            asm volatile("cp.async.commit_group;" ::: "memory");
        }

        if (t >= 2 * qt) {
            #pragma unroll
            for (int mt = 0; mt < 2; ++mt)
                #pragma unroll
                for (int nt = 0; nt < 4; ++nt)
                    #pragma unroll
                    for (int q = 0; q < 4; ++q) {
                        const int row = q0 + wm + mt * 16 + (q >> 1) * 8 + lr4;
                        const int col = kv0 + wn + nt * 8 + lc4 * 2 + (q & 1);
                        if (col > row) sacc[mt][nt][q] = -1e30f;
                    }
        }

        float pmax[4];
        #pragma unroll
        for (int r = 0; r < 4; ++r) pmax[r] = -INFINITY;
        #pragma unroll
        for (int mt = 0; mt < 2; ++mt)
            #pragma unroll
            for (int nt = 0; nt < 4; ++nt)
                #pragma unroll
                for (int q = 0; q < 4; ++q)
                    pmax[mt * 2 + (q >> 1)] = fmaxf(pmax[mt * 2 + (q >> 1)], sacc[mt][nt][q]);
        #pragma unroll
        for (int r = 0; r < 4; ++r) {
            pmax[r] = fmaxf(pmax[r], __shfl_xor_sync(0xffffffffu, pmax[r], 1));
            pmax[r] = fmaxf(pmax[r], __shfl_xor_sync(0xffffffffu, pmax[r], 2));
        }
        if (lc4 == 0) {
            #pragma unroll
            for (int r = 0; r < 4; ++r) {
                const int rl = wm + (r >> 1) * 16 + (r & 1) * 8 + lr4;
                mred[wnid * 128 + rl] = pmax[r];
            }
        }
        __syncthreads();

        float corr[4], psum[4];
        #pragma unroll
        for (int r = 0; r < 4; ++r) {
            const int rl = wm + (r >> 1) * 16 + (r & 1) * 8 + lr4;
            const float mnew = fmaxf(m_i[r], fmaxf(mred[rl], mred[128 + rl]));
            corr[r] = __expf(m_i[r] - mnew);
            m_i[r] = mnew;
            psum[r] = 0.0f;
        }
        #pragma unroll
        for (int mt = 0; mt < 2; ++mt)
            #pragma unroll
            for (int nt = 0; nt < 4; ++nt)
                #pragma unroll
                for (int h = 0; h < 2; ++h) {
                    const int r = mt * 2 + h;
                    const float p0 = __expf(sacc[mt][nt][h * 2]     - m_i[r]);
                    const float p1 = __expf(sacc[mt][nt][h * 2 + 1] - m_i[r]);
                    psum[r] += p0 + p1;
                    const int rl = wm + mt * 16 + h * 8 + lr4;
                    *(float2*)(Ps + rl * LDP + wn + nt * 8 + lc4 * 2) =
                        make_float2(tf32f(p0), tf32f(p1));
                }
        #pragma unroll
        for (int r = 0; r < 4; ++r) {
            psum[r] += __shfl_xor_sync(0xffffffffu, psum[r], 1);
            psum[r] += __shfl_xor_sync(0xffffffffu, psum[r], 2);
        }
        if (lc4 == 0) {
            #pragma unroll
            for (int r = 0; r < 4; ++r) {
                const int rl = wm + (r >> 1) * 16 + (r & 1) * 8 + lr4;
                lred[wnid * 128 + rl] = psum[r];
            }
        }
        #pragma unroll
        for (int mt = 0; mt < 2; ++mt)
            #pragma unroll
            for (int nt = 0; nt < 8; ++nt)
                #pragma unroll
                for (int q = 0; q < 4; ++q)
                    oacc[mt][nt][q] *= corr[mt * 2 + (q >> 1)];

        if (havek) asm volatile("cp.async.wait_group 1;" ::: "memory");
        else       asm volatile("cp.async.wait_group 0;" ::: "memory");
        __syncthreads();

        #pragma unroll
        for (int r = 0; r < 4; ++r) {
            const int rl = wm + (r >> 1) * 16 + (r & 1) * 8 + lr4;
            l_i[r] = l_i[r] * corr[r] + lred[rl] + lred[128 + rl];
        }

        #pragma unroll
        for (int kk = 0; kk < 8; ++kk) {
            const int k0 = kk * 8;
            uint32_t a[2][4], b[8][2];
            #pragma unroll
            for (int mt = 0; mt < 2; ++mt) {
                const float* ap = Ps + (wm + mt * 16 + lr4) * LDP + k0 + lc4;
                a[mt][0] = __float_as_uint(ap[0]);
                a[mt][1] = __float_as_uint(ap[8 * LDP]);
                a[mt][2] = __float_as_uint(ap[4]);
                a[mt][3] = __float_as_uint(ap[8 * LDP + 4]);
            }
            #pragma unroll
            for (int nt = 0; nt < 8; ++nt) {
                const float* bp = Vs + (k0 + lc4) * LDV + wno + nt * 8 + lr4;
                b[nt][0] = __float_as_uint(bp[0]);
                b[nt][1] = __float_as_uint(bp[4 * LDV]);
            }
            #pragma unroll
            for (int mt = 0; mt < 2; ++mt)
                #pragma unroll
                for (int nt = 0; nt < 8; ++nt)
                    mma_tf32(oacc[mt][nt], a[mt], b[nt]);
        }
    }

    // epilogue: normalize, tf32-round (consumed by final tf32 GEMM), store
    #pragma unroll
    for (int mt = 0; mt < 2; ++mt)
        #pragma unroll
        for (int h = 0; h < 2; ++h) {
            const int r = mt * 2 + h;
            const int row = q0 + wm + mt * 16 + h * 8 + lr4;
            const float inv = 1.0f / l_i[r];
            float* op = Out + ((size_t)bz * T_ + row) * D_ + head * HD_ + wno + lc4 * 2;
            #pragma unroll
            for (int nt = 0; nt < 8; ++nt)
                *(float2*)(op + nt * 8) =
                    make_float2(tf32f(oacc[mt][nt][h * 2] * inv),
                                tf32f(oacc[mt][nt][h * 2 + 1] * inv));
        }
}

// ---------------------------------------------------------------------------
// Launch
// ---------------------------------------------------------------------------
extern "C" void kernel_launch(void* const* d_in, const int* in_sizes, int n_in,
                              void* d_out, int out_size)
{
    const float* x  = (const float*)d_in[0];
    const float* wn = (const float*)d_in[2];
    const float* wq = (const float*)d_in[3];
    const float* wk = (const float*)d_in[4];
    const float* wv = (const float*)d_in[5];
    const float* wo = (const float*)d_in[6];
    float* out = (float*)d_out;

    float* base = nullptr;
    cudaGetSymbolAddress((void**)&base, g_scratch);
    float* xn  = base;
    float* qkv = base + 1ull * BTD_;          // q, k, v contiguous
    float* qb  = qkv;
    float* kb  = base + 2ull * BTD_;
    float* vb  = base + 3ull * BTD_;
    float* ao  = base + 4ull * BTD_;
    float* rwq = base + 5ull * BTD_;
    float* rwk = rwq + DD_;
    float* rwv = rwk + DD_;
    float* rwo = rwv + DD_;

    cudaFuncSetAttribute(gemm_qkv, cudaFuncAttributeMaxDynamicSharedMemorySize,
                         GEMM_SMEM_BYTES);
    cudaFuncSetAttribute(gemm_out, cudaFuncAttributeMaxDynamicSharedMemorySize,
                         GEMM_SMEM_BYTES);
    cudaFuncSetAttribute(attn_mma, cudaFuncAttributeMaxDynamicSharedMemorySize,
                         ATT_SMEM_BYTES);

    const int nblk = DD_ / 4 / 256;     // 4096
    round_tf32_kernel<<<nblk, 256>>>((const float4*)wq, (float4*)rwq);
    round_tf32_kernel<<<nblk, 256>>>((const float4*)wk, (float4*)rwk);
    round_tf32_kernel<<<nblk, 256>>>((const float4*)wv, (float4*)rwv);
    round_tf32_kernel<<<nblk, 256>>>((const float4*)wo, (float4*)rwo);

    rmsnorm_kernel<<<BT_, 256>>>(x, wn, xn);

    gemm_qkv<<<dim3(48, BT_ / 128), 256, GEMM_SMEM_BYTES>>>(xn, rwq, rwk, rwv, qkv);

    attn_mma<<<dim3(T_ / 128, B_ * H_), 256, ATT_SMEM_BYTES>>>(qb, kb, vb, ao);

    gemm_out<<<dim3(D_ / 128, BT_ / 128), 256, GEMM_SMEM_BYTES>>>(ao, rwo, out);
}

// round 6
// speedup vs baseline: 4.4217x; 1.0094x over previous
#include <cuda_runtime.h>
#include <math.h>
#include <stdint.h>

#define B_ 2
#define T_ 2048
#define D_ 2048
#define H_ 16
#define HD_ 128
#define BT_ (B_ * T_)
#define BTD_ (B_ * T_ * D_)
#define DD_ (D_ * D_)

// Scratch: xn, q, k, v, attn_out (5 x 33.5MB) + 4 tf32-rounded weights
__device__ float g_scratch[5ull * BTD_ + 4ull * DD_];

// ---------------------------------------------------------------------------
// helpers
// ---------------------------------------------------------------------------
__device__ __forceinline__ uint32_t smem_u32(const void* p) {
    uint32_t a;
    asm("{ .reg .u64 t; cvta.to.shared.u64 t, %1; cvt.u32.u64 %0, t; }"
        : "=r"(a) : "l"(p));
    return a;
}

__device__ __forceinline__ void cp16(uint32_t s, const void* g) {
    asm volatile("cp.async.cg.shared.global [%0], [%1], 16;"
                 :: "r"(s), "l"(g) : "memory");
}

__device__ __forceinline__ uint32_t cvt_tf32(float x) {
    uint32_t r;
    asm("cvt.rna.tf32.f32 %0, %1;" : "=r"(r) : "f"(x));
    return r;
}

__device__ __forceinline__ float tf32f(float x) {
    return __uint_as_float(cvt_tf32(x));
}

__device__ __forceinline__ void mma_tf32(float* c, const uint32_t* a, const uint32_t* b) {
    asm volatile(
        "mma.sync.aligned.m16n8k8.row.col.f32.tf32.tf32.f32 "
        "{%0,%1,%2,%3}, {%4,%5,%6,%7}, {%8,%9}, {%0,%1,%2,%3};"
        : "+f"(c[0]), "+f"(c[1]), "+f"(c[2]), "+f"(c[3])
        : "r"(a[0]), "r"(a[1]), "r"(a[2]), "r"(a[3]), "r"(b[0]), "r"(b[1]));
}

// ---------------------------------------------------------------------------
// tf32 pre-rounding of all 4 weight matrices in one launch
// ---------------------------------------------------------------------------
__global__ void __launch_bounds__(256) round4_kernel(
    const float4* __restrict__ s0, const float4* __restrict__ s1,
    const float4* __restrict__ s2, const float4* __restrict__ s3,
    float4* __restrict__ dst)
{
    const int m = blockIdx.x >> 12;                 // 4096 blocks per matrix
    const int i = (blockIdx.x & 4095) * 256 + threadIdx.x;
    const float4* src = (m == 0) ? s0 : (m == 1) ? s1 : (m == 2) ? s2 : s3;
    float4 v = src[i];
    v.x = tf32f(v.x); v.y = tf32f(v.y); v.z = tf32f(v.z); v.w = tf32f(v.w);
    dst[(size_t)m * (DD_ / 4) + i] = v;
}

// ---------------------------------------------------------------------------
// RMSNorm: one block per row of D=2048; output tf32-rounded
// ---------------------------------------------------------------------------
__global__ void __launch_bounds__(256) rmsnorm_kernel(
    const float* __restrict__ x, const float* __restrict__ w, float* __restrict__ out)
{
    const int row = blockIdx.x;
    const float4* xr = (const float4*)(x + (size_t)row * D_);
    float4* orow = (float4*)(out + (size_t)row * D_);
    const float4* w4 = (const float4*)w;
    const int tid = threadIdx.x;

    float4 v0 = xr[tid];
    float4 v1 = xr[tid + 256];
    float ss = v0.x*v0.x + v0.y*v0.y + v0.z*v0.z + v0.w*v0.w
             + v1.x*v1.x + v1.y*v1.y + v1.z*v1.z + v1.w*v1.w;

    #pragma unroll
    for (int m = 16; m > 0; m >>= 1) ss += __shfl_xor_sync(0xffffffffu, ss, m);

    __shared__ float red[8];
    if ((tid & 31) == 0) red[tid >> 5] = ss;
    __syncthreads();
    float tot = red[0] + red[1] + red[2] + red[3] + red[4] + red[5] + red[6] + red[7];

    const float inv = 1.0f / (sqrtf(tot) * 0.022097086912079612f + 1e-8f);

    float4 w0 = w4[tid], w1 = w4[tid + 256];
    float4 o0, o1;
    o0.x = tf32f(v0.x * w0.x * inv); o0.y = tf32f(v0.y * w0.y * inv);
    o0.z = tf32f(v0.z * w0.z * inv); o0.w = tf32f(v0.w * w0.w * inv);
    o1.x = tf32f(v1.x * w1.x * inv); o1.y = tf32f(v1.y * w1.y * inv);
    o1.z = tf32f(v1.z * w1.z * inv); o1.w = tf32f(v1.w * w1.w * inv);
    orow[tid] = o0;
    orow[tid + 256] = o1;
}

// ---------------------------------------------------------------------------
// tf32 mma.sync GEMM core. 128x128x32 CTA tile, 8 warps (2x4), 64x32 warp tile.
// 3-stage cp.async pipeline, 1 sync per k-tile, double-buffered fragments.
// ---------------------------------------------------------------------------
#define LDW 36
#define STG (2 * 128 * LDW)                 // floats per stage (A then B)
#define GEMM_SMEM_BYTES (3 * STG * 4)       // 110592
#define NKT 64

struct GemmAcc { float acc[4][4][4]; };

__device__ __forceinline__ void gemm_core(
    const float* __restrict__ A, const float* __restrict__ W,
    int bm, int bn, float* sm, GemmAcc& g)
{
    const int tid = threadIdx.x;
    const int lane = tid & 31;
    const int wid = tid >> 5;
    const int wm = (wid & 1) * 64;
    const int wn = (wid >> 1) * 32;
    const int lr4 = lane >> 2;
    const int lc4 = lane & 3;

    const int r0 = tid >> 3;                // 0..31
    const int c16 = tid & 7;                // 0..7
    const float* Ag = A + (size_t)(bm * 128 + r0) * 2048 + c16 * 4;
    const float* Wg = W + (size_t)(bn * 128 + r0) * 2048 + c16 * 4;
    const uint32_t sbase = smem_u32(sm);
    uint32_t soff[4];
    #pragma unroll
    for (int i = 0; i < 4; ++i)
        soff[i] = ((uint32_t)(r0 + 32 * i) * LDW + c16 * 4) * 4;

    #pragma unroll
    for (int mt = 0; mt < 4; ++mt)
        #pragma unroll
        for (int nt = 0; nt < 4; ++nt)
            #pragma unroll
            for (int q = 0; q < 4; ++q) g.acc[mt][nt][q] = 0.0f;

    // prologue: k-tiles 0,1 into stages 0,1
    #pragma unroll
    for (int j = 0; j < 2; ++j) {
        const uint32_t st = sbase + (uint32_t)(j * STG) * 4;
        const float* ag = Ag + j * 32;
        const float* wg = Wg + j * 32;
        #pragma unroll
        for (int i = 0; i < 4; ++i) cp16(st + soff[i], ag + (size_t)(32 * i) * 2048);
        #pragma unroll
        for (int i = 0; i < 4; ++i) cp16(st + 128 * LDW * 4 + soff[i], wg + (size_t)(32 * i) * 2048);
        asm volatile("cp.async.commit_group;" ::: "memory");
    }

    int s = 0;
    for (int kt = 0; kt < NKT; ++kt) {
        if (kt < NKT - 1) asm volatile("cp.async.wait_group 1;" ::: "memory");
        else              asm volatile("cp.async.wait_group 0;" ::: "memory");
        __syncthreads();   // also guards overwrite of stage (kt+2)%3 == stage of kt-1

        if (kt + 2 < NKT) {
            const int s2 = (s + 2 >= 3) ? s - 1 : s + 2;
            const uint32_t st = sbase + (uint32_t)(s2 * STG) * 4;
            const float* ag = Ag + (kt + 2) * 32;
            const float* wg = Wg + (kt + 2) * 32;
            #pragma unroll
            for (int i = 0; i < 4; ++i) cp16(st + soff[i], ag + (size_t)(32 * i) * 2048);
            #pragma unroll
            for (int i = 0; i < 4; ++i) cp16(st + 128 * LDW * 4 + soff[i], wg + (size_t)(32 * i) * 2048);
            asm volatile("cp.async.commit_group;" ::: "memory");
        }

        const float* Ast = sm + s * STG;
        const float* Bst = Ast + 128 * LDW;

        // fragment double-buffer: load kk+1 before MMAs of kk
        uint32_t a[2][4][4], b[2][4][2];
        #pragma unroll
        for (int mt = 0; mt < 4; ++mt) {
            const float* ap = Ast + (wm + mt * 16 + lr4) * LDW + lc4;
            a[0][mt][0] = __float_as_uint(ap[0]);
            a[0][mt][1] = __float_as_uint(ap[8 * LDW]);
            a[0][mt][2] = __float_as_uint(ap[4]);
            a[0][mt][3] = __float_as_uint(ap[8 * LDW + 4]);
        }
        #pragma unroll
        for (int nt = 0; nt < 4; ++nt) {
            const float* bp = Bst + (wn + nt * 8 + lr4) * LDW + lc4;
            b[0][nt][0] = __float_as_uint(bp[0]);
            b[0][nt][1] = __float_as_uint(bp[4]);
        }
        #pragma unroll
        for (int kk = 0; kk < 4; ++kk) {
            const int cur = kk & 1;
            if (kk < 3) {
                const int k1 = (kk + 1) * 8;
                const int nxt = cur ^ 1;
                #pragma unroll
                for (int mt = 0; mt < 4; ++mt) {
                    const float* ap = Ast + (wm + mt * 16 + lr4) * LDW + k1 + lc4;
                    a[nxt][mt][0] = __float_as_uint(ap[0]);
                    a[nxt][mt][1] = __float_as_uint(ap[8 * LDW]);
                    a[nxt][mt][2] = __float_as_uint(ap[4]);
                    a[nxt][mt][3] = __float_as_uint(ap[8 * LDW + 4]);
                }
                #pragma unroll
                for (int nt = 0; nt < 4; ++nt) {
                    const float* bp = Bst + (wn + nt * 8 + lr4) * LDW + k1 + lc4;
                    b[nxt][nt][0] = __float_as_uint(bp[0]);
                    b[nxt][nt][1] = __float_as_uint(bp[4]);
                }
            }
            #pragma unroll
            for (int mt = 0; mt < 4; ++mt)
                #pragma unroll
                for (int nt = 0; nt < 4; ++nt)
                    mma_tf32(g.acc[mt][nt], a[cur][mt], b[cur][nt]);
        }
        s = (s + 1 == 3) ? 0 : s + 1;
    }
}

// Fused QKV: grid (48, 32); bn>>4 selects weight & output. [B,H,T,HD], tf32.
__global__ void __launch_bounds__(256, 2) gemm_qkv(
    const float* __restrict__ A, const float* __restrict__ Wq,
    const float* __restrict__ Wk, const float* __restrict__ Wv,
    float* __restrict__ QKV)
{
    extern __shared__ float sm[];
    const int bm = blockIdx.y;
    const int sel = blockIdx.x >> 4;
    const int bn = blockIdx.x & 15;
    const float* W = (sel == 0) ? Wq : (sel == 1) ? Wk : Wv;
    float* C = QKV + (size_t)sel * BTD_;

    GemmAcc g;
    gemm_core(A, W, bm, bn, sm, g);

    const int lane = threadIdx.x & 31;
    const int wid = threadIdx.x >> 5;
    const int wm = (wid & 1) * 64;
    const int wn = (wid >> 1) * 32;
    const int rbase = bm * 128 + wm + (lane >> 2);
    const int cbase = wn + (lane & 3) * 2;
    #pragma unroll
    for (int mt = 0; mt < 4; ++mt)
        #pragma unroll
        for (int half = 0; half < 2; ++half) {
            const int row = rbase + mt * 16 + half * 8;
            const int b = row >> 11;
            const int t = row & (T_ - 1);
            float* cp = C + (((size_t)(b * H_ + bn)) * T_ + t) * HD_ + cbase;
            #pragma unroll
            for (int nt = 0; nt < 4; ++nt)
                *(float2*)(cp + nt * 8) =
                    make_float2(tf32f(g.acc[mt][nt][half * 2]),
                                tf32f(g.acc[mt][nt][half * 2 + 1]));
        }
}

// Final projection: row-major fp32 store.
__global__ void __launch_bounds__(256, 2) gemm_out(
    const float* __restrict__ A, const float* __restrict__ W, float* __restrict__ C)
{
    extern __shared__ float sm[];
    const int bm = blockIdx.y, bn = blockIdx.x;

    GemmAcc g;
    gemm_core(A, W, bm, bn, sm, g);

    const int lane = threadIdx.x & 31;
    const int wid = threadIdx.x >> 5;
    const int wm = (wid & 1) * 64;
    const int wn = (wid >> 1) * 32;
    const int rbase = bm * 128 + wm + (lane >> 2);
    const int cbase = wn + (lane & 3) * 2;
    #pragma unroll
    for (int mt = 0; mt < 4; ++mt)
        #pragma unroll
        for (int half = 0; half < 2; ++half) {
            const int row = rbase + mt * 16 + half * 8;
            float* cp = C + (size_t)row * D_ + bn * 128 + cbase;
            #pragma unroll
            for (int nt = 0; nt < 4; ++nt)
                *(float2*)(cp + nt * 8) =
                    make_float2(g.acc[mt][nt][half * 2], g.acc[mt][nt][half * 2 + 1]);
        }
}

// ---------------------------------------------------------------------------
// Tensor-core flash attention (tf32 mma.sync, causal).
// CTA: 128 q-rows; kv step 64; 8 warps (4 M x 2 N). Inputs pre-rounded tf32.
// ---------------------------------------------------------------------------
#define LDQ 132
#define LDK 132
#define LDV 136
#define LDP 68
#define QS_OFF 0
#define KS_OFF 16896
#define KS_STAGE 8448
#define VS_OFF (KS_OFF + 2 * KS_STAGE)
#define PS_OFF (VS_OFF + 64 * LDV)
#define MR_OFF (PS_OFF + 128 * LDP)
#define LR_OFF (MR_OFF + 256)
#define ATT_SMEM_FLOATS (LR_OFF + 256)
#define ATT_SMEM_BYTES (ATT_SMEM_FLOATS * 4)
#define ATT_SCALE 0.08838834764831845f

__global__ void __launch_bounds__(256, 1) attn_mma(
    const float* __restrict__ Q, const float* __restrict__ K,
    const float* __restrict__ V, float* __restrict__ Out)
{
    extern __shared__ float sm[];
    float* Qs = sm + QS_OFF;
    float* Ks = sm + KS_OFF;
    float* Vs = sm + VS_OFF;
    float* Ps = sm + PS_OFF;
    float* mred = sm + MR_OFF;
    float* lred = sm + LR_OFF;

    const int qt = (int)gridDim.x - 1 - (int)blockIdx.x;
    const int bh = blockIdx.y;
    const int bz = bh >> 4;
    const int head = bh & (H_ - 1);
    const int q0 = qt * 128;
    const int tid = threadIdx.x;
    const int lane = tid & 31;
    const int wid = tid >> 5;
    const int wm = (wid & 3) * 32;
    const int wn = (wid >> 2) * 32;
    const int wno = (wid >> 2) * 64;
    const int wnid = wid >> 2;
    const int lr4 = lane >> 2;
    const int lc4 = lane & 3;

    const float* Qg = Q + ((size_t)bh * T_ + q0) * HD_;
    const float* Kg = K + (size_t)bh * T_ * HD_;
    const float* Vg = V + (size_t)bh * T_ * HD_;

    #pragma unroll
    for (int j = 0; j < 16; ++j) {
        const int i = tid + j * 256;
        const int r = i >> 5;
        const int c = (i & 31) << 2;
        float4 v = *(const float4*)(Qg + r * HD_ + c);
        float* d = Qs + r * LDQ + c;
        d[0] = tf32f(v.x * ATT_SCALE);
        d[1] = tf32f(v.y * ATT_SCALE);
        d[2] = tf32f(v.z * ATT_SCALE);
        d[3] = tf32f(v.w * ATT_SCALE);
    }

    int ldr[8], ldc[8];
    #pragma unroll
    for (int j = 0; j < 8; ++j) {
        const int i = tid + j * 256;
        ldr[j] = i >> 5;
        ldc[j] = (i & 31) << 2;
    }
    const uint32_t sKs = smem_u32(Ks);
    const uint32_t sVs = smem_u32(Vs);

    const int ntiles = 2 * (qt + 1);

    #pragma unroll
    for (int j = 0; j < 8; ++j)
        cp16(sKs + (uint32_t)(ldr[j] * LDK + ldc[j]) * 4, Kg + (size_t)ldr[j] * HD_ + ldc[j]);
    asm volatile("cp.async.commit_group;" ::: "memory");

    float m_i[4], l_i[4];
    float oacc[2][8][4];
    #pragma unroll
    for (int r = 0; r < 4; ++r) { m_i[r] = -INFINITY; l_i[r] = 0.0f; }
    #pragma unroll
    for (int mt = 0; mt < 2; ++mt)
        #pragma unroll
        for (int nt = 0; nt < 8; ++nt)
            #pragma unroll
            for (int q = 0; q < 4; ++q) oacc[mt][nt][q] = 0.0f;

    for (int t = 0; t < ntiles; ++t) {
        const int kv0 = t * 64;
        const int st = t & 1;

        asm volatile("cp.async.wait_group 0;" ::: "memory");
        __syncthreads();

        {
            const float* vg = Vg + (size_t)kv0 * HD_;
            #pragma unroll
            for (int j = 0; j < 8; ++j)
                cp16(sVs + (uint32_t)(ldr[j] * LDV + ldc[j]) * 4, vg + (size_t)ldr[j] * HD_ + ldc[j]);
            asm volatile("cp.async.commit_group;" ::: "memory");
        }

        float sacc[2][4][4];
        #pragma unroll
        for (int mt = 0; mt < 2; ++mt)
            #pragma unroll
            for (int nt = 0; nt < 4; ++nt)
                #pragma unroll
                for (int q = 0; q < 4; ++q) sacc[mt][nt][q] = 0.0f;

        const float* Kst = Ks + st * KS_STAGE;
        #pragma unroll
        for (int kk = 0; kk < 16; ++kk) {
            const int k0 = kk * 8;
            uint32_t a[2][4], b[4][2];
            #pragma unroll
            for (int mt = 0; mt < 2; ++mt) {
                const float* ap = Qs + (wm + mt * 16 + lr4) * LDQ + k0 + lc4;
                a[mt][0] = __float_as_uint(ap[0]);
                a[mt][1] = __float_as_uint(ap[8 * LDQ]);
                a[mt][2] = __float_as_uint(ap[4]);
                a[mt][3] = __float_as_uint(ap[8 * LDQ + 4]);
            }
            #pragma unroll
            for (int nt = 0; nt < 4; ++nt) {
                const float* bp = Kst + (wn + nt * 8 + lr4) * LDK + k0 + lc4;
                b[nt][0] = __float_as_uint(bp[0]);
                b[nt][1] = __float_as_uint(bp[4]);
            }
            #pragma unroll
            for (int mt = 0; mt < 2; ++mt)
                #pragma unroll
                for (int nt = 0; nt < 4; ++nt)
                    mma_tf32(sacc[mt][nt], a[mt], b[nt]);
        }

        const bool havek = (t + 1 < ntiles);
        if (havek) {
            const float* kg = Kg + (size_t)(kv0 + 64) * HD_;
            const uint32_t kb = sKs + (uint32_t)((st ^ 1) * KS_STAGE) * 4;
            #pragma unroll
            for (int j = 0; j < 8; ++j)
                cp16(kb + (uint32_t)(ldr[j] * LDK + ldc[j]) * 4, kg + (size_t)ldr[j] * HD_ + ldc[j]);
            asm volatile("cp.async.commit_group;" ::: "memory");
        }

        if (t >= 2 * qt) {
            #pragma unroll
            for (int mt = 0; mt < 2; ++mt)
                #pragma unroll
                for (int nt = 0; nt < 4; ++nt)
                    #pragma unroll
                    for (int q = 0; q < 4; ++q) {
                        const int row = q0 + wm + mt * 16 + (q >> 1) * 8 + lr4;
                        const int col = kv0 + wn + nt * 8 + lc4 * 2 + (q & 1);
                        if (col > row) sacc[mt][nt][q] = -1e30f;
                    }
        }

        float pmax[4];
        #pragma unroll
        for (int r = 0; r < 4; ++r) pmax[r] = -INFINITY;
        #pragma unroll
        for (int mt = 0; mt < 2; ++mt)
            #pragma unroll
            for (int nt = 0; nt < 4; ++nt)
                #pragma unroll
                for (int q = 0; q < 4; ++q)
                    pmax[mt * 2 + (q >> 1)] = fmaxf(pmax[mt * 2 + (q >> 1)], sacc[mt][nt][q]);
        #pragma unroll
        for (int r = 0; r < 4; ++r) {
            pmax[r] = fmaxf(pmax[r], __shfl_xor_sync(0xffffffffu, pmax[r], 1));
            pmax[r] = fmaxf(pmax[r], __shfl_xor_sync(0xffffffffu, pmax[r], 2));
        }
        if (lc4 == 0) {
            #pragma unroll
            for (int r = 0; r < 4; ++r) {
                const int rl = wm + (r >> 1) * 16 + (r & 1) * 8 + lr4;
                mred[wnid * 128 + rl] = pmax[r];
            }
        }
        __syncthreads();

        float corr[4], psum[4];
        #pragma unroll
        for (int r = 0; r < 4; ++r) {
            const int rl = wm + (r >> 1) * 16 + (r & 1) * 8 + lr4;
            const float mnew = fmaxf(m_i[r], fmaxf(mred[rl], mred[128 + rl]));
            corr[r] = __expf(m_i[r] - mnew);
            m_i[r] = mnew;
            psum[r] = 0.0f;
        }
        #pragma unroll
        for (int mt = 0; mt < 2; ++mt)
            #pragma unroll
            for (int nt = 0; nt < 4; ++nt)
                #pragma unroll
                for (int h = 0; h < 2; ++h) {
                    const int r = mt * 2 + h;
                    const float p0 = __expf(sacc[mt][nt][h * 2]     - m_i[r]);
                    const float p1 = __expf(sacc[mt][nt][h * 2 + 1] - m_i[r]);
                    psum[r] += p0 + p1;
                    const int rl = wm + mt * 16 + h * 8 + lr4;
                    *(float2*)(Ps + rl * LDP + wn + nt * 8 + lc4 * 2) =
                        make_float2(tf32f(p0), tf32f(p1));
                }
        #pragma unroll
        for (int r = 0; r < 4; ++r) {
            psum[r] += __shfl_xor_sync(0xffffffffu, psum[r], 1);
            psum[r] += __shfl_xor_sync(0xffffffffu, psum[r], 2);
        }
        if (lc4 == 0) {
            #pragma unroll
            for (int r = 0; r < 4; ++r) {
                const int rl = wm + (r >> 1) * 16 + (r & 1) * 8 + lr4;
                lred[wnid * 128 + rl] = psum[r];
            }
        }
        #pragma unroll
        for (int mt = 0; mt < 2; ++mt)
            #pragma unroll
            for (int nt = 0; nt < 8; ++nt)
                #pragma unroll
                for (int q = 0; q < 4; ++q)
                    oacc[mt][nt][q] *= corr[mt * 2 + (q >> 1)];

        if (havek) asm volatile("cp.async.wait_group 1;" ::: "memory");
        else       asm volatile("cp.async.wait_group 0;" ::: "memory");
        __syncthreads();

        #pragma unroll
        for (int r = 0; r < 4; ++r) {
            const int rl = wm + (r >> 1) * 16 + (r & 1) * 8 + lr4;
            l_i[r] = l_i[r] * corr[r] + lred[rl] + lred[128 + rl];
        }

        #pragma unroll
        for (int kk = 0; kk < 8; ++kk) {
            const int k0 = kk * 8;
            uint32_t a[2][4], b[8][2];
            #pragma unroll
            for (int mt = 0; mt < 2; ++mt) {
                const float* ap = Ps + (wm + mt * 16 + lr4) * LDP + k0 + lc4;
                a[mt][0] = __float_as_uint(ap[0]);
                a[mt][1] = __float_as_uint(ap[8 * LDP]);
                a[mt][2] = __float_as_uint(ap[4]);
                a[mt][3] = __float_as_uint(ap[8 * LDP + 4]);
            }
            #pragma unroll
            for (int nt = 0; nt < 8; ++nt) {
                const float* bp = Vs + (k0 + lc4) * LDV + wno + nt * 8 + lr4;
                b[nt][0] = __float_as_uint(bp[0]);
                b[nt][1] = __float_as_uint(bp[4 * LDV]);
            }
            #pragma unroll
            for (int mt = 0; mt < 2; ++mt)
                #pragma unroll
                for (int nt = 0; nt < 8; ++nt)
                    mma_tf32(oacc[mt][nt], a[mt], b[nt]);
        }
    }

    #pragma unroll
    for (int mt = 0; mt < 2; ++mt)
        #pragma unroll
        for (int h = 0; h < 2; ++h) {
            const int r = mt * 2 + h;
            const int row = q0 + wm + mt * 16 + h * 8 + lr4;
            const float inv = 1.0f / l_i[r];
            float* op = Out + ((size_t)bz * T_ + row) * D_ + head * HD_ + wno + lc4 * 2;
            #pragma unroll
            for (int nt = 0; nt < 8; ++nt)
                *(float2*)(op + nt * 8) =
                    make_float2(tf32f(oacc[mt][nt][h * 2] * inv),
                                tf32f(oacc[mt][nt][h * 2 + 1] * inv));
        }
}

// ---------------------------------------------------------------------------
// Launch
// ---------------------------------------------------------------------------
extern "C" void kernel_launch(void* const* d_in, const int* in_sizes, int n_in,
                              void* d_out, int out_size)
{
    const float* x  = (const float*)d_in[0];
    const float* wn = (const float*)d_in[2];
    const float* wq = (const float*)d_in[3];
    const float* wk = (const float*)d_in[4];
    const float* wv = (const float*)d_in[5];
    const float* wo = (const float*)d_in[6];
    float* out = (float*)d_out;

    float* base = nullptr;
    cudaGetSymbolAddress((void**)&base, g_scratch);
    float* xn  = base;
    float* qkv = base + 1ull * BTD_;
    float* qb  = qkv;
    float* kb  = base + 2ull * BTD_;
    float* vb  = base + 3ull * BTD_;
    float* ao  = base + 4ull * BTD_;
    float* rw  = base + 5ull * BTD_;          // rwq, rwk, rwv, rwo contiguous
    float* rwq = rw;
    float* rwk = rw + 1ull * DD_;
    float* rwv = rw + 2ull * DD_;
    float* rwo = rw + 3ull * DD_;

    cudaFuncSetAttribute(gemm_qkv, cudaFuncAttributeMaxDynamicSharedMemorySize,
                         GEMM_SMEM_BYTES);
    cudaFuncSetAttribute(gemm_out, cudaFuncAttributeMaxDynamicSharedMemorySize,
                         GEMM_SMEM_BYTES);
    cudaFuncSetAttribute(attn_mma, cudaFuncAttributeMaxDynamicSharedMemorySize,
                         ATT_SMEM_BYTES);

    round4_kernel<<<4 * (DD_ / 4 / 256), 256>>>(
        (const float4*)wq, (const float4*)wk, (const float4*)wv, (const float4*)wo,
        (float4*)rw);

    rmsnorm_kernel<<<BT_, 256>>>(x, wn, xn);

    gemm_qkv<<<dim3(48, BT_ / 128), 256, GEMM_SMEM_BYTES>>>(xn, rwq, rwk, rwv, qkv);

    attn_mma<<<dim3(T_ / 128, B_ * H_), 256, ATT_SMEM_BYTES>>>(qb, kb, vb, ao);

    gemm_out<<<dim3(D_ / 128, BT_ / 128), 256, GEMM_SMEM_BYTES>>>(ao, rwo, out);
}

// round 7
// speedup vs baseline: 8.8399x; 1.9992x over previous
#include <cuda_runtime.h>
#include <cuda_fp16.h>
#include <math.h>
#include <stdint.h>

#define B_ 2
#define T_ 2048
#define D_ 2048
#define H_ 16
#define HD_ 128
#define BT_ (B_ * T_)
#define BTD_ (B_ * T_ * D_)
#define DD_ (D_ * D_)

// Scratch (halves): xn, q, k, v, attn_out (5 x BTD) + 4 fp16 weights (4 x DD)
__device__ __half g_scratch_h[5ull * BTD_ + 4ull * DD_];

// ---------------------------------------------------------------------------
// helpers
// ---------------------------------------------------------------------------
__device__ __forceinline__ uint32_t smem_u32(const void* p) {
    uint32_t a;
    asm("{ .reg .u64 t; cvta.to.shared.u64 t, %1; cvt.u32.u64 %0, t; }"
        : "=r"(a) : "l"(p));
    return a;
}

__device__ __forceinline__ void cp16(uint32_t s, const void* g) {
    asm volatile("cp.async.cg.shared.global [%0], [%1], 16;"
                 :: "r"(s), "l"(g) : "memory");
}

#define LDSM4(R, addr) \
    asm volatile("ldmatrix.sync.aligned.m8n8.x4.shared.b16 {%0,%1,%2,%3}, [%4];" \
        : "=r"((R)[0]), "=r"((R)[1]), "=r"((R)[2]), "=r"((R)[3]) : "r"(addr))

#define LDSM4T(R, addr) \
    asm volatile("ldmatrix.sync.aligned.m8n8.x4.trans.shared.b16 {%0,%1,%2,%3}, [%4];" \
        : "=r"((R)[0]), "=r"((R)[1]), "=r"((R)[2]), "=r"((R)[3]) : "r"(addr))

__device__ __forceinline__ void mma_f16(float* c, const uint32_t* a, const uint32_t* b) {
    asm volatile(
        "mma.sync.aligned.m16n8k16.row.col.f32.f16.f16.f32 "
        "{%0,%1,%2,%3}, {%4,%5,%6,%7}, {%8,%9}, {%0,%1,%2,%3};"
        : "+f"(c[0]), "+f"(c[1]), "+f"(c[2]), "+f"(c[3])
        : "r"(a[0]), "r"(a[1]), "r"(a[2]), "r"(a[3]), "r"(b[0]), "r"(b[1]));
}

// ---------------------------------------------------------------------------
// fp16 pre-rounding of all 4 weight matrices in one launch
// ---------------------------------------------------------------------------
__global__ void __launch_bounds__(256) round4_kernel(
    const float4* __restrict__ s0, const float4* __restrict__ s1,
    const float4* __restrict__ s2, const float4* __restrict__ s3,
    __half* __restrict__ dst)
{
    const int m = blockIdx.x >> 12;
    const int i = (blockIdx.x & 4095) * 256 + threadIdx.x;
    const float4* src = (m == 0) ? s0 : (m == 1) ? s1 : (m == 2) ? s2 : s3;
    float4 v = src[i];
    __half* d = dst + (size_t)m * DD_ + (size_t)i * 4;
    *(__half2*)d       = __floats2half2_rn(v.x, v.y);
    *(__half2*)(d + 2) = __floats2half2_rn(v.z, v.w);
}

// ---------------------------------------------------------------------------
// RMSNorm: one block per row of D=2048; output fp16
// ---------------------------------------------------------------------------
__global__ void __launch_bounds__(256) rmsnorm_kernel(
    const float* __restrict__ x, const float* __restrict__ w, __half* __restrict__ out)
{
    const int row = blockIdx.x;
    const float4* xr = (const float4*)(x + (size_t)row * D_);
    __half* orow = out + (size_t)row * D_;
    const float4* w4 = (const float4*)w;
    const int tid = threadIdx.x;

    float4 v0 = xr[tid];
    float4 v1 = xr[tid + 256];
    float ss = v0.x*v0.x + v0.y*v0.y + v0.z*v0.z + v0.w*v0.w
             + v1.x*v1.x + v1.y*v1.y + v1.z*v1.z + v1.w*v1.w;

    #pragma unroll
    for (int m = 16; m > 0; m >>= 1) ss += __shfl_xor_sync(0xffffffffu, ss, m);

    __shared__ float red[8];
    if ((tid & 31) == 0) red[tid >> 5] = ss;
    __syncthreads();
    float tot = red[0] + red[1] + red[2] + red[3] + red[4] + red[5] + red[6] + red[7];

    const float inv = 1.0f / (sqrtf(tot) * 0.022097086912079612f + 1e-8f);

    float4 w0 = w4[tid], w1 = w4[tid + 256];
    *(__half2*)(orow + tid * 4)     = __floats2half2_rn(v0.x * w0.x * inv, v0.y * w0.y * inv);
    *(__half2*)(orow + tid * 4 + 2) = __floats2half2_rn(v0.z * w0.z * inv, v0.w * w0.w * inv);
    *(__half2*)(orow + (tid + 256) * 4)     = __floats2half2_rn(v1.x * w1.x * inv, v1.y * w1.y * inv);
    *(__half2*)(orow + (tid + 256) * 4 + 2) = __floats2half2_rn(v1.z * w1.z * inv, v1.w * w1.w * inv);
}

// ---------------------------------------------------------------------------
// fp16 mma.sync GEMM core. 128x128x64 CTA tile, 8 warps (2x4), 64x32 warp tile.
// 3-stage cp.async, ldmatrix fragments, m16n8k16.
// ---------------------------------------------------------------------------
#define LDW 72                              // halves per row (64 + 8 pad)
#define AB_BYTES (128 * LDW * 2)            // one matrix per stage: 18432 B
#define STG_BYTES (2 * AB_BYTES)            // 36864 B
#define GEMM_SMEM_BYTES (3 * STG_BYTES)     // 110592 B
#define NKT 32                              // 2048 / 64

struct GemmAcc { float acc[4][4][4]; };

__device__ __forceinline__ void gemm_core(
    const __half* __restrict__ A, const __half* __restrict__ W,
    int bm, int bn, __half* sm, GemmAcc& g)
{
    const int tid = threadIdx.x;
    const int lane = tid & 31;
    const int wid = tid >> 5;
    const int wm = (wid & 1) * 64;
    const int wn = (wid >> 1) * 32;

    // gmem loads: 4 x 16B chunks per matrix per stage
    const int r0 = tid >> 3;                // 0..31
    const int c8 = tid & 7;                 // chunk of 8 halves
    const __half* Ag = A + (size_t)(bm * 128 + r0) * 2048 + c8 * 8;
    const __half* Wg = W + (size_t)(bn * 128 + r0) * 2048 + c8 * 8;
    const uint32_t sbase = smem_u32(sm);
    uint32_t soff[4];
    #pragma unroll
    for (int i = 0; i < 4; ++i)
        soff[i] = ((uint32_t)(r0 + 32 * i) * LDW + c8 * 8) * 2;

    // ldmatrix per-thread components
    const int arow = (lane & 7) + ((lane >> 3) & 1) * 8;
    const int akoff = (lane >> 4) * 8;
    const uint32_t a_off = ((uint32_t)(wm + arow) * LDW + akoff) * 2;
    const int brow = (lane & 7) + ((lane >> 4) << 3);
    const int bkoff = ((lane >> 3) & 1) * 8;
    const uint32_t b_off = AB_BYTES + ((uint32_t)(wn + brow) * LDW + bkoff) * 2;

    #pragma unroll
    for (int mt = 0; mt < 4; ++mt)
        #pragma unroll
        for (int nt = 0; nt < 4; ++nt)
            #pragma unroll
            for (int q = 0; q < 4; ++q) g.acc[mt][nt][q] = 0.0f;

    // prologue: k-tiles 0,1 into stages 0,1
    #pragma unroll
    for (int j = 0; j < 2; ++j) {
        const uint32_t st = sbase + (uint32_t)j * STG_BYTES;
        #pragma unroll
        for (int i = 0; i < 4; ++i) cp16(st + soff[i], Ag + (size_t)(32 * i) * 2048 + j * 64);
        #pragma unroll
        for (int i = 0; i < 4; ++i) cp16(st + AB_BYTES + soff[i], Wg + (size_t)(32 * i) * 2048 + j * 64);
        asm volatile("cp.async.commit_group;" ::: "memory");
    }

    int s = 0;
    for (int kt = 0; kt < NKT; ++kt) {
        if (kt < NKT - 1) asm volatile("cp.async.wait_group 1;" ::: "memory");
        else              asm volatile("cp.async.wait_group 0;" ::: "memory");
        __syncthreads();

        if (kt + 2 < NKT) {
            const int s2 = (s + 2 >= 3) ? s - 1 : s + 2;
            const uint32_t st = sbase + (uint32_t)s2 * STG_BYTES;
            const __half* ag = Ag + (kt + 2) * 64;
            const __half* wg = Wg + (kt + 2) * 64;
            #pragma unroll
            for (int i = 0; i < 4; ++i) cp16(st + soff[i], ag + (size_t)(32 * i) * 2048);
            #pragma unroll
            for (int i = 0; i < 4; ++i) cp16(st + AB_BYTES + soff[i], wg + (size_t)(32 * i) * 2048);
            asm volatile("cp.async.commit_group;" ::: "memory");
        }

        const uint32_t stb = sbase + (uint32_t)s * STG_BYTES;
        #pragma unroll
        for (int ks = 0; ks < 4; ++ks) {
            uint32_t a[4][4], b[2][4];
            #pragma unroll
            for (int mt = 0; mt < 4; ++mt)
                LDSM4(a[mt], stb + a_off + (uint32_t)(mt * 16 * LDW + ks * 16) * 2);
            #pragma unroll
            for (int ntp = 0; ntp < 2; ++ntp)
                LDSM4(b[ntp], stb + b_off + (uint32_t)(ntp * 16 * LDW + ks * 16) * 2);
            #pragma unroll
            for (int mt = 0; mt < 4; ++mt)
                #pragma unroll
                for (int nt = 0; nt < 4; ++nt)
                    mma_f16(g.acc[mt][nt], a[mt], b[nt >> 1] + (nt & 1) * 2);
        }
        s = (s + 1 == 3) ? 0 : s + 1;
    }
}

#define ATT_SCALE 0.08838834764831845f

// Fused QKV: grid (48, 32); bn>>4 selects weight & output. [B,H,T,HD] fp16.
// Q (sel 0) is pre-scaled by ATT_SCALE.
__global__ void __launch_bounds__(256, 2) gemm_qkv(
    const __half* __restrict__ A, const __half* __restrict__ Wq,
    const __half* __restrict__ Wk, const __half* __restrict__ Wv,
    __half* __restrict__ QKV)
{
    extern __shared__ __half smh[];
    const int bm = blockIdx.y;
    const int sel = blockIdx.x >> 4;
    const int bn = blockIdx.x & 15;
    const __half* W = (sel == 0) ? Wq : (sel == 1) ? Wk : Wv;
    __half* C = QKV + (size_t)sel * BTD_;
    const float scale = (sel == 0) ? ATT_SCALE : 1.0f;

    GemmAcc g;
    gemm_core(A, W, bm, bn, smh, g);

    const int lane = threadIdx.x & 31;
    const int wid = threadIdx.x >> 5;
    const int wm = (wid & 1) * 64;
    const int wn = (wid >> 1) * 32;
    const int rbase = bm * 128 + wm + (lane >> 2);
    const int cbase = wn + (lane & 3) * 2;
    #pragma unroll
    for (int mt = 0; mt < 4; ++mt)
        #pragma unroll
        for (int half = 0; half < 2; ++half) {
            const int row = rbase + mt * 16 + half * 8;
            const int b = row >> 11;
            const int t = row & (T_ - 1);
            __half* cp = C + (((size_t)(b * H_ + bn)) * T_ + t) * HD_ + cbase;
            #pragma unroll
            for (int nt = 0; nt < 4; ++nt)
                *(__half2*)(cp + nt * 8) =
                    __floats2half2_rn(g.acc[mt][nt][half * 2] * scale,
                                      g.acc[mt][nt][half * 2 + 1] * scale);
        }
}

// Final projection: fp32 row-major store.
__global__ void __launch_bounds__(256, 2) gemm_out(
    const __half* __restrict__ A, const __half* __restrict__ W, float* __restrict__ C)
{
    extern __shared__ __half smh[];
    const int bm = blockIdx.y, bn = blockIdx.x;

    GemmAcc g;
    gemm_core(A, W, bm, bn, smh, g);

    const int lane = threadIdx.x & 31;
    const int wid = threadIdx.x >> 5;
    const int wm = (wid & 1) * 64;
    const int wn = (wid >> 1) * 32;
    const int rbase = bm * 128 + wm + (lane >> 2);
    const int cbase = wn + (lane & 3) * 2;
    #pragma unroll
    for (int mt = 0; mt < 4; ++mt)
        #pragma unroll
        for (int half = 0; half < 2; ++half) {
            const int row = rbase + mt * 16 + half * 8;
            float* cp = C + (size_t)row * D_ + bn * 128 + cbase;
            #pragma unroll
            for (int nt = 0; nt < 4; ++nt)
                *(float2*)(cp + nt * 8) =
                    make_float2(g.acc[mt][nt][half * 2], g.acc[mt][nt][half * 2 + 1]);
        }
}

// ---------------------------------------------------------------------------
// fp16 tensor-core flash attention (causal). CTA: 128 q-rows; kv step 64;
// 8 warps (4 M x 2 N). Q pre-scaled fp16; ldmatrix fragments; trans for V.
// ---------------------------------------------------------------------------
#define LDQ 136
#define LDK 136
#define LDV 136
#define LDP 72
#define QS_B 0
#define QS_BYTES (128 * LDQ * 2)          // 34816
#define KS_B QS_BYTES
#define KSTB (64 * LDK * 2)               // 17408
#define VS_B (KS_B + 2 * KSTB)            // 69632
#define PS_B (VS_B + 64 * LDV * 2)        // 87040
#define RED_B (PS_B + 128 * LDP * 2)      // 105472
#define ATT_SMEM_BYTES (RED_B + 2048)     // 107520

__global__ void __launch_bounds__(256, 1) attn_mma(
    const __half* __restrict__ Q, const __half* __restrict__ K,
    const __half* __restrict__ V, __half* __restrict__ Out)
{
    extern __shared__ __half smh[];
    const uint32_t sbase = smem_u32(smh);
    const uint32_t sQ = sbase + QS_B;
    const uint32_t sK = sbase + KS_B;
    const uint32_t sV = sbase + VS_B;
    const uint32_t sP = sbase + PS_B;
    __half* Ps = (__half*)((char*)smh + PS_B);
    float* mred = (float*)((char*)smh + RED_B);
    float* lred = mred + 256;

    const int qt = (int)gridDim.x - 1 - (int)blockIdx.x;
    const int bh = blockIdx.y;
    const int bz = bh >> 4;
    const int head = bh & (H_ - 1);
    const int q0 = qt * 128;
    const int tid = threadIdx.x;
    const int lane = tid & 31;
    const int wid = tid >> 5;
    const int wm = (wid & 3) * 32;
    const int wn = (wid >> 2) * 32;
    const int wno = (wid >> 2) * 64;
    const int wnid = wid >> 2;
    const int lr4 = lane >> 2;
    const int lc4 = lane & 3;

    const __half* Qg = Q + ((size_t)bh * T_ + q0) * HD_;
    const __half* Kg = K + (size_t)bh * T_ * HD_;
    const __half* Vg = V + (size_t)bh * T_ * HD_;

    // ldmatrix per-thread address components
    const int arow = (lane & 7) + ((lane >> 3) & 1) * 8;
    const int akoff = (lane >> 4) * 8;
    const uint32_t qa_off = ((uint32_t)(wm + arow) * LDQ + akoff) * 2;
    const uint32_t pa_off = ((uint32_t)(wm + arow) * LDP + akoff) * 2;
    const int brow = (lane & 7) + ((lane >> 4) << 3);
    const int bkoff = ((lane >> 3) & 1) * 8;
    const uint32_t kb_off = ((uint32_t)(wn + brow) * LDK + bkoff) * 2;
    const int vrow = (lane & 7) + ((lane >> 3) & 1) * 8;
    const int vcoff = (lane >> 4) * 8;
    const uint32_t vb_off = ((uint32_t)vrow * LDV + wno + vcoff) * 2;

    // gmem chunk geometry
    const int gr = tid >> 4;          // 0..15
    const int gc = tid & 15;          // chunk of 8 halves

    // prologue: Q (8 chunks) + K(0) (4 chunks), one group
    #pragma unroll
    for (int i = 0; i < 8; ++i)
        cp16(sQ + ((uint32_t)(gr + 16 * i) * LDQ + gc * 8) * 2,
             Qg + (size_t)(gr + 16 * i) * HD_ + gc * 8);
    #pragma unroll
    for (int i = 0; i < 4; ++i)
        cp16(sK + ((uint32_t)(gr + 16 * i) * LDK + gc * 8) * 2,
             Kg + (size_t)(gr + 16 * i) * HD_ + gc * 8);
    asm volatile("cp.async.commit_group;" ::: "memory");

    const int ntiles = 2 * (qt + 1);

    float m_i[4], l_i[4];
    float oacc[2][8][4];
    #pragma unroll
    for (int r = 0; r < 4; ++r) { m_i[r] = -INFINITY; l_i[r] = 0.0f; }
    #pragma unroll
    for (int mt = 0; mt < 2; ++mt)
        #pragma unroll
        for (int nt = 0; nt < 8; ++nt)
            #pragma unroll
            for (int q = 0; q < 4; ++q) oacc[mt][nt][q] = 0.0f;

    for (int t = 0; t < ntiles; ++t) {
        const int kv0 = t * 64;
        const int st = t & 1;

        asm volatile("cp.async.wait_group 0;" ::: "memory");
        __syncthreads();

        // launch V(t)
        {
            const __half* vg = Vg + (size_t)kv0 * HD_;
            #pragma unroll
            for (int i = 0; i < 4; ++i)
                cp16(sV + ((uint32_t)(gr + 16 * i) * LDV + gc * 8) * 2,
                     vg + (size_t)(gr + 16 * i) * HD_ + gc * 8);
            asm volatile("cp.async.commit_group;" ::: "memory");
        }

        // S = Q @ K^T
        float sacc[2][4][4];
        #pragma unroll
        for (int mt = 0; mt < 2; ++mt)
            #pragma unroll
            for (int nt = 0; nt < 4; ++nt)
                #pragma unroll
                for (int q = 0; q < 4; ++q) sacc[mt][nt][q] = 0.0f;

        const uint32_t sKst = sK + (uint32_t)st * KSTB;
        #pragma unroll
        for (int ks = 0; ks < 8; ++ks) {
            uint32_t a[2][4], b[2][4];
            #pragma unroll
            for (int mt = 0; mt < 2; ++mt)
                LDSM4(a[mt], sQ + qa_off + (uint32_t)(mt * 16 * LDQ + ks * 16) * 2);
            #pragma unroll
            for (int ntp = 0; ntp < 2; ++ntp)
                LDSM4(b[ntp], sKst + kb_off + (uint32_t)(ntp * 16 * LDK + ks * 16) * 2);
            #pragma unroll
            for (int mt = 0; mt < 2; ++mt)
                #pragma unroll
                for (int nt = 0; nt < 4; ++nt)
                    mma_f16(sacc[mt][nt], a[mt], b[nt >> 1] + (nt & 1) * 2);
        }

        // prefetch K(t+1)
        const bool havek = (t + 1 < ntiles);
        if (havek) {
            const __half* kg = Kg + (size_t)(kv0 + 64) * HD_;
            const uint32_t kb = sK + (uint32_t)((st ^ 1) * KSTB);
            #pragma unroll
            for (int i = 0; i < 4; ++i)
                cp16(kb + ((uint32_t)(gr + 16 * i) * LDK + gc * 8) * 2,
                     kg + (size_t)(gr + 16 * i) * HD_ + gc * 8);
            asm volatile("cp.async.commit_group;" ::: "memory");
        }

        // causal mask on diagonal-region tiles
        if (t >= 2 * qt) {
            #pragma unroll
            for (int mt = 0; mt < 2; ++mt)
                #pragma unroll
                for (int nt = 0; nt < 4; ++nt)
                    #pragma unroll
                    for (int q = 0; q < 4; ++q) {
                        const int row = q0 + wm + mt * 16 + (q >> 1) * 8 + lr4;
                        const int col = kv0 + wn + nt * 8 + lc4 * 2 + (q & 1);
                        if (col > row) sacc[mt][nt][q] = -1e30f;
                    }
        }

        // row max
        float pmax[4];
        #pragma unroll
        for (int r = 0; r < 4; ++r) pmax[r] = -INFINITY;
        #pragma unroll
        for (int mt = 0; mt < 2; ++mt)
            #pragma unroll
            for (int nt = 0; nt < 4; ++nt)
                #pragma unroll
                for (int q = 0; q < 4; ++q)
                    pmax[mt * 2 + (q >> 1)] = fmaxf(pmax[mt * 2 + (q >> 1)], sacc[mt][nt][q]);
        #pragma unroll
        for (int r = 0; r < 4; ++r) {
            pmax[r] = fmaxf(pmax[r], __shfl_xor_sync(0xffffffffu, pmax[r], 1));
            pmax[r] = fmaxf(pmax[r], __shfl_xor_sync(0xffffffffu, pmax[r], 2));
        }
        if (lc4 == 0) {
            #pragma unroll
            for (int r = 0; r < 4; ++r) {
                const int rl = wm + (r >> 1) * 16 + (r & 1) * 8 + lr4;
                mred[wnid * 128 + rl] = pmax[r];
            }
        }
        __syncthreads();

        // exp, write P (fp16), partial sums
        float corr[4], psum[4];
        #pragma unroll
        for (int r = 0; r < 4; ++r) {
            const int rl = wm + (r >> 1) * 16 + (r & 1) * 8 + lr4;
            const float mnew = fmaxf(m_i[r], fmaxf(mred[rl], mred[128 + rl]));
            corr[r] = __expf(m_i[r] - mnew);
            m_i[r] = mnew;
            psum[r] = 0.0f;
        }
        #pragma unroll
        for (int mt = 0; mt < 2; ++mt)
            #pragma unroll
            for (int nt = 0; nt < 4; ++nt)
                #pragma unroll
                for (int h = 0; h < 2; ++h) {
                    const int r = mt * 2 + h;
                    const float p0 = __expf(sacc[mt][nt][h * 2]     - m_i[r]);
                    const float p1 = __expf(sacc[mt][nt][h * 2 + 1] - m_i[r]);
                    psum[r] += p0 + p1;
                    const int rl = wm + mt * 16 + h * 8 + lr4;
                    *(__half2*)(Ps + (size_t)rl * LDP + wn + nt * 8 + lc4 * 2) =
                        __floats2half2_rn(p0, p1);
                }
        #pragma unroll
        for (int r = 0; r < 4; ++r) {
            psum[r] += __shfl_xor_sync(0xffffffffu, psum[r], 1);
            psum[r] += __shfl_xor_sync(0xffffffffu, psum[r], 2);
        }
        if (lc4 == 0) {
            #pragma unroll
            for (int r = 0; r < 4; ++r) {
                const int rl = wm + (r >> 1) * 16 + (r & 1) * 8 + lr4;
                lred[wnid * 128 + rl] = psum[r];
            }
        }
        #pragma unroll
        for (int mt = 0; mt < 2; ++mt)
            #pragma unroll
            for (int nt = 0; nt < 8; ++nt)
                #pragma unroll
                for (int q = 0; q < 4; ++q)
                    oacc[mt][nt][q] *= corr[mt * 2 + (q >> 1)];

        if (havek) asm volatile("cp.async.wait_group 1;" ::: "memory");
        else       asm volatile("cp.async.wait_group 0;" ::: "memory");
        __syncthreads();

        #pragma unroll
        for (int r = 0; r < 4; ++r) {
            const int rl = wm + (r >> 1) * 16 + (r & 1) * 8 + lr4;
            l_i[r] = l_i[r] * corr[r] + lred[rl] + lred[128 + rl];
        }

        // O += P @ V  (ldmatrix.trans on row-major V gives B-fragments of V^T)
        #pragma unroll
        for (int ks = 0; ks < 4; ++ks) {
            uint32_t a[2][4], b[4][4];
            #pragma unroll
            for (int mt = 0; mt < 2; ++mt)
                LDSM4(a[mt], sP + pa_off + (uint32_t)(mt * 16 * LDP + ks * 16) * 2);
            #pragma unroll
            for (int ntq = 0; ntq < 4; ++ntq)
                LDSM4T(b[ntq], sV + vb_off + (uint32_t)(ks * 16 * LDV + ntq * 16) * 2);
            #pragma unroll
            for (int mt = 0; mt < 2; ++mt)
                #pragma unroll
                for (int nt = 0; nt < 8; ++nt)
                    mma_f16(oacc[mt][nt], a[mt], b[nt >> 1] + (nt & 1) * 2);
        }
    }

    // epilogue: normalize, fp16 store (consumed by final fp16 GEMM)
    #pragma unroll
    for (int mt = 0; mt < 2; ++mt)
        #pragma unroll
        for (int h = 0; h < 2; ++h) {
            const int r = mt * 2 + h;
            const int row = q0 + wm + mt * 16 + h * 8 + lr4;
            const float inv = 1.0f / l_i[r];
            __half* op = Out + ((size_t)bz * T_ + row) * D_ + head * HD_ + wno + lc4 * 2;
            #pragma unroll
            for (int nt = 0; nt < 8; ++nt)
                *(__half2*)(op + nt * 8) =
                    __floats2half2_rn(oacc[mt][nt][h * 2] * inv,
                                      oacc[mt][nt][h * 2 + 1] * inv);
        }
}

// ---------------------------------------------------------------------------
// Launch
// ---------------------------------------------------------------------------
extern "C" void kernel_launch(void* const* d_in, const int* in_sizes, int n_in,
                              void* d_out, int out_size)
{
    const float* x  = (const float*)d_in[0];
    const float* wn = (const float*)d_in[2];
    const float* wq = (const float*)d_in[3];
    const float* wk = (const float*)d_in[4];
    const float* wv = (const float*)d_in[5];
    const float* wo = (const float*)d_in[6];
    float* out = (float*)d_out;

    __half* base = nullptr;
    cudaGetSymbolAddress((void**)&base, g_scratch_h);
    __half* xn  = base;
    __half* qkv = base + 1ull * BTD_;
    __half* qb  = qkv;
    __half* kb  = base + 2ull * BTD_;
    __half* vb  = base + 3ull * BTD_;
    __half* ao  = base + 4ull * BTD_;
    __half* rw  = base + 5ull * BTD_;
    __half* rwq = rw;
    __half* rwk = rw + 1ull * DD_;
    __half* rwv = rw + 2ull * DD_;
    __half* rwo = rw + 3ull * DD_;

    cudaFuncSetAttribute(gemm_qkv, cudaFuncAttributeMaxDynamicSharedMemorySize,
                         GEMM_SMEM_BYTES);
    cudaFuncSetAttribute(gemm_out, cudaFuncAttributeMaxDynamicSharedMemorySize,
                         GEMM_SMEM_BYTES);
    cudaFuncSetAttribute(attn_mma, cudaFuncAttributeMaxDynamicSharedMemorySize,
                         ATT_SMEM_BYTES);

    round4_kernel<<<4 * (DD_ / 4 / 256), 256>>>(
        (const float4*)wq, (const float4*)wk, (const float4*)wv, (const float4*)wo, rw);

    rmsnorm_kernel<<<BT_, 256>>>(x, wn, xn);

    gemm_qkv<<<dim3(48, BT_ / 128), 256, GEMM_SMEM_BYTES>>>(xn, rwq, rwk, rwv, qkv);

    attn_mma<<<dim3(T_ / 128, B_ * H_), 256, ATT_SMEM_BYTES>>>(qb, kb, vb, ao);

    gemm_out<<<dim3(D_ / 128, BT_ / 128), 256, GEMM_SMEM_BYTES>>>(ao, rwo, out);
}

// round 8
// speedup vs baseline: 8.9765x; 1.0155x over previous
#include <cuda_runtime.h>
#include <cuda_fp16.h>
#include <math.h>
#include <stdint.h>

#define B_ 2
#define T_ 2048
#define D_ 2048
#define H_ 16
#define HD_ 128
#define BT_ (B_ * T_)
#define BTD_ (B_ * T_ * D_)
#define DD_ (D_ * D_)

// Scratch (halves): xn, q, k, v, attn_out (5 x BTD) + 4 fp16 weights (4 x DD)
__device__ __half g_scratch_h[5ull * BTD_ + 4ull * DD_];

// ---------------------------------------------------------------------------
// helpers
// ---------------------------------------------------------------------------
__device__ __forceinline__ uint32_t smem_u32(const void* p) {
    uint32_t a;
    asm("{ .reg .u64 t; cvta.to.shared.u64 t, %1; cvt.u32.u64 %0, t; }"
        : "=r"(a) : "l"(p));
    return a;
}

__device__ __forceinline__ void cp16(uint32_t s, const void* g) {
    asm volatile("cp.async.cg.shared.global [%0], [%1], 16;"
                 :: "r"(s), "l"(g) : "memory");
}

#define LDSM4(R, addr) \
    asm volatile("ldmatrix.sync.aligned.m8n8.x4.shared.b16 {%0,%1,%2,%3}, [%4];" \
        : "=r"((R)[0]), "=r"((R)[1]), "=r"((R)[2]), "=r"((R)[3]) : "r"(addr))

#define LDSM4T(R, addr) \
    asm volatile("ldmatrix.sync.aligned.m8n8.x4.trans.shared.b16 {%0,%1,%2,%3}, [%4];" \
        : "=r"((R)[0]), "=r"((R)[1]), "=r"((R)[2]), "=r"((R)[3]) : "r"(addr))

__device__ __forceinline__ void mma_f16(float* c, const uint32_t* a, const uint32_t* b) {
    asm volatile(
        "mma.sync.aligned.m16n8k16.row.col.f32.f16.f16.f32 "
        "{%0,%1,%2,%3}, {%4,%5,%6,%7}, {%8,%9}, {%0,%1,%2,%3};"
        : "+f"(c[0]), "+f"(c[1]), "+f"(c[2]), "+f"(c[3])
        : "r"(a[0]), "r"(a[1]), "r"(a[2]), "r"(a[3]), "r"(b[0]), "r"(b[1]));
}

__device__ __forceinline__ uint32_t packh2(float lo, float hi) {
    __half2 h = __floats2half2_rn(lo, hi);
    return *(uint32_t*)&h;
}

// ---------------------------------------------------------------------------
// fp16 pre-rounding of all 4 weight matrices in one launch
// ---------------------------------------------------------------------------
__global__ void __launch_bounds__(256) round4_kernel(
    const float4* __restrict__ s0, const float4* __restrict__ s1,
    const float4* __restrict__ s2, const float4* __restrict__ s3,
    __half* __restrict__ dst)
{
    const int m = blockIdx.x >> 12;
    const int i = (blockIdx.x & 4095) * 256 + threadIdx.x;
    const float4* src = (m == 0) ? s0 : (m == 1) ? s1 : (m == 2) ? s2 : s3;
    float4 v = src[i];
    __half* d = dst + (size_t)m * DD_ + (size_t)i * 4;
    *(__half2*)d       = __floats2half2_rn(v.x, v.y);
    *(__half2*)(d + 2) = __floats2half2_rn(v.z, v.w);
}

// ---------------------------------------------------------------------------
// RMSNorm: one block per row of D=2048; output fp16
// ---------------------------------------------------------------------------
__global__ void __launch_bounds__(256) rmsnorm_kernel(
    const float* __restrict__ x, const float* __restrict__ w, __half* __restrict__ out)
{
    const int row = blockIdx.x;
    const float4* xr = (const float4*)(x + (size_t)row * D_);
    __half* orow = out + (size_t)row * D_;
    const float4* w4 = (const float4*)w;
    const int tid = threadIdx.x;

    float4 v0 = xr[tid];
    float4 v1 = xr[tid + 256];
    float ss = v0.x*v0.x + v0.y*v0.y + v0.z*v0.z + v0.w*v0.w
             + v1.x*v1.x + v1.y*v1.y + v1.z*v1.z + v1.w*v1.w;

    #pragma unroll
    for (int m = 16; m > 0; m >>= 1) ss += __shfl_xor_sync(0xffffffffu, ss, m);

    __shared__ float red[8];
    if ((tid & 31) == 0) red[tid >> 5] = ss;
    __syncthreads();
    float tot = red[0] + red[1] + red[2] + red[3] + red[4] + red[5] + red[6] + red[7];

    const float inv = 1.0f / (sqrtf(tot) * 0.022097086912079612f + 1e-8f);

    float4 w0 = w4[tid], w1 = w4[tid + 256];
    *(__half2*)(orow + tid * 4)     = __floats2half2_rn(v0.x * w0.x * inv, v0.y * w0.y * inv);
    *(__half2*)(orow + tid * 4 + 2) = __floats2half2_rn(v0.z * w0.z * inv, v0.w * w0.w * inv);
    *(__half2*)(orow + (tid + 256) * 4)     = __floats2half2_rn(v1.x * w1.x * inv, v1.y * w1.y * inv);
    *(__half2*)(orow + (tid + 256) * 4 + 2) = __floats2half2_rn(v1.z * w1.z * inv, v1.w * w1.w * inv);
}

// ---------------------------------------------------------------------------
// fp16 mma.sync GEMM core. 128x128x64 CTA tile, 8 warps (2x4), 64x32 warp tile.
// 3-stage cp.async, ldmatrix fragments, m16n8k16.
// ---------------------------------------------------------------------------
#define LDW 72                              // halves per row (64 + 8 pad)
#define AB_BYTES (128 * LDW * 2)            // one matrix per stage: 18432 B
#define STG_BYTES (2 * AB_BYTES)            // 36864 B
#define GEMM_SMEM_BYTES (3 * STG_BYTES)     // 110592 B
#define NKT 32                              // 2048 / 64

struct GemmAcc { float acc[4][4][4]; };

__device__ __forceinline__ void gemm_core(
    const __half* __restrict__ A, const __half* __restrict__ W,
    int bm, int bn, __half* sm, GemmAcc& g)
{
    const int tid = threadIdx.x;
    const int lane = tid & 31;
    const int wid = tid >> 5;
    const int wm = (wid & 1) * 64;
    const int wn = (wid >> 1) * 32;

    const int r0 = tid >> 3;
    const int c8 = tid & 7;
    const __half* Ag = A + (size_t)(bm * 128 + r0) * 2048 + c8 * 8;
    const __half* Wg = W + (size_t)(bn * 128 + r0) * 2048 + c8 * 8;
    const uint32_t sbase = smem_u32(sm);
    uint32_t soff[4];
    #pragma unroll
    for (int i = 0; i < 4; ++i)
        soff[i] = ((uint32_t)(r0 + 32 * i) * LDW + c8 * 8) * 2;

    const int arow = (lane & 7) + ((lane >> 3) & 1) * 8;
    const int akoff = (lane >> 4) * 8;
    const uint32_t a_off = ((uint32_t)(wm + arow) * LDW + akoff) * 2;
    const int brow = (lane & 7) + ((lane >> 4) << 3);
    const int bkoff = ((lane >> 3) & 1) * 8;
    const uint32_t b_off = AB_BYTES + ((uint32_t)(wn + brow) * LDW + bkoff) * 2;

    #pragma unroll
    for (int mt = 0; mt < 4; ++mt)
        #pragma unroll
        for (int nt = 0; nt < 4; ++nt)
            #pragma unroll
            for (int q = 0; q < 4; ++q) g.acc[mt][nt][q] = 0.0f;

    #pragma unroll
    for (int j = 0; j < 2; ++j) {
        const uint32_t st = sbase + (uint32_t)j * STG_BYTES;
        #pragma unroll
        for (int i = 0; i < 4; ++i) cp16(st + soff[i], Ag + (size_t)(32 * i) * 2048 + j * 64);
        #pragma unroll
        for (int i = 0; i < 4; ++i) cp16(st + AB_BYTES + soff[i], Wg + (size_t)(32 * i) * 2048 + j * 64);
        asm volatile("cp.async.commit_group;" ::: "memory");
    }

    int s = 0;
    for (int kt = 0; kt < NKT; ++kt) {
        if (kt < NKT - 1) asm volatile("cp.async.wait_group 1;" ::: "memory");
        else              asm volatile("cp.async.wait_group 0;" ::: "memory");
        __syncthreads();

        if (kt + 2 < NKT) {
            const int s2 = (s + 2 >= 3) ? s - 1 : s + 2;
            const uint32_t st = sbase + (uint32_t)s2 * STG_BYTES;
            const __half* ag = Ag + (kt + 2) * 64;
            const __half* wg = Wg + (kt + 2) * 64;
            #pragma unroll
            for (int i = 0; i < 4; ++i) cp16(st + soff[i], ag + (size_t)(32 * i) * 2048);
            #pragma unroll
            for (int i = 0; i < 4; ++i) cp16(st + AB_BYTES + soff[i], wg + (size_t)(32 * i) * 2048);
            asm volatile("cp.async.commit_group;" ::: "memory");
        }

        const uint32_t stb = sbase + (uint32_t)s * STG_BYTES;
        #pragma unroll
        for (int ks = 0; ks < 4; ++ks) {
            uint32_t a[4][4], b[2][4];
            #pragma unroll
            for (int mt = 0; mt < 4; ++mt)
                LDSM4(a[mt], stb + a_off + (uint32_t)(mt * 16 * LDW + ks * 16) * 2);
            #pragma unroll
            for (int ntp = 0; ntp < 2; ++ntp)
                LDSM4(b[ntp], stb + b_off + (uint32_t)(ntp * 16 * LDW + ks * 16) * 2);
            #pragma unroll
            for (int mt = 0; mt < 4; ++mt)
                #pragma unroll
                for (int nt = 0; nt < 4; ++nt)
                    mma_f16(g.acc[mt][nt], a[mt], b[nt >> 1] + (nt & 1) * 2);
        }
        s = (s + 1 == 3) ? 0 : s + 1;
    }
}

#define ATT_SCALE 0.08838834764831845f

// Fused QKV: grid (48, 32); bn>>4 selects weight & output. [B,H,T,HD] fp16.
// Q (sel 0) is pre-scaled by ATT_SCALE.
__global__ void __launch_bounds__(256, 2) gemm_qkv(
    const __half* __restrict__ A, const __half* __restrict__ Wq,
    const __half* __restrict__ Wk, const __half* __restrict__ Wv,
    __half* __restrict__ QKV)
{
    extern __shared__ __half smh[];
    const int bm = blockIdx.y;
    const int sel = blockIdx.x >> 4;
    const int bn = blockIdx.x & 15;
    const __half* W = (sel == 0) ? Wq : (sel == 1) ? Wk : Wv;
    __half* C = QKV + (size_t)sel * BTD_;
    const float scale = (sel == 0) ? ATT_SCALE : 1.0f;

    GemmAcc g;
    gemm_core(A, W, bm, bn, smh, g);

    const int lane = threadIdx.x & 31;
    const int wid = threadIdx.x >> 5;
    const int wm = (wid & 1) * 64;
    const int wn = (wid >> 1) * 32;
    const int rbase = bm * 128 + wm + (lane >> 2);
    const int cbase = wn + (lane & 3) * 2;
    #pragma unroll
    for (int mt = 0; mt < 4; ++mt)
        #pragma unroll
        for (int half = 0; half < 2; ++half) {
            const int row = rbase + mt * 16 + half * 8;
            const int b = row >> 11;
            const int t = row & (T_ - 1);
            __half* cp = C + (((size_t)(b * H_ + bn)) * T_ + t) * HD_ + cbase;
            #pragma unroll
            for (int nt = 0; nt < 4; ++nt)
                *(__half2*)(cp + nt * 8) =
                    __floats2half2_rn(g.acc[mt][nt][half * 2] * scale,
                                      g.acc[mt][nt][half * 2 + 1] * scale);
        }
}

// Final projection: fp32 row-major store.
__global__ void __launch_bounds__(256, 2) gemm_out(
    const __half* __restrict__ A, const __half* __restrict__ W, float* __restrict__ C)
{
    extern __shared__ __half smh[];
    const int bm = blockIdx.y, bn = blockIdx.x;

    GemmAcc g;
    gemm_core(A, W, bm, bn, smh, g);

    const int lane = threadIdx.x & 31;
    const int wid = threadIdx.x >> 5;
    const int wm = (wid & 1) * 64;
    const int wn = (wid >> 1) * 32;
    const int rbase = bm * 128 + wm + (lane >> 2);
    const int cbase = wn + (lane & 3) * 2;
    #pragma unroll
    for (int mt = 0; mt < 4; ++mt)
        #pragma unroll
        for (int half = 0; half < 2; ++half) {
            const int row = rbase + mt * 16 + half * 8;
            float* cp = C + (size_t)row * D_ + bn * 128 + cbase;
            #pragma unroll
            for (int nt = 0; nt < 4; ++nt)
                *(float2*)(cp + nt * 8) =
                    make_float2(g.acc[mt][nt][half * 2], g.acc[mt][nt][half * 2 + 1]);
        }
}

// ---------------------------------------------------------------------------
// fp16 flash attention, FA2-style: 8 M-warps x 16 q-rows, kv step 64.
// P stays in registers (S-accum fragment == PV A-operand fragment layout).
// Double-buffered K and V; ONE __syncthreads per kv tile; intra-warp softmax.
// ---------------------------------------------------------------------------
#define LDA 136
#define QS_BYTES (128 * LDA * 2)            // 34816
#define KSTB (64 * LDA * 2)                 // 17408
#define KS_B QS_BYTES
#define VS_B (KS_B + 2 * KSTB)
#define ATT_SMEM_BYTES (VS_B + 2 * KSTB)    // 104448

__global__ void __launch_bounds__(256, 1) attn_mma(
    const __half* __restrict__ Q, const __half* __restrict__ K,
    const __half* __restrict__ V, __half* __restrict__ Out)
{
    extern __shared__ __half smh[];
    const uint32_t sbase = smem_u32(smh);
    const uint32_t sQ = sbase;
    const uint32_t sK = sbase + KS_B;
    const uint32_t sV = sbase + VS_B;

    const int qt = (int)gridDim.x - 1 - (int)blockIdx.x;   // heavy tiles first
    const int bh = blockIdx.y;
    const int bz = bh >> 4;
    const int head = bh & (H_ - 1);
    const int q0 = qt * 128;
    const int tid = threadIdx.x;
    const int lane = tid & 31;
    const int wid = tid >> 5;
    const int wm = wid * 16;                 // warp owns q rows [wm, wm+16)
    const int lr4 = lane >> 2;
    const int lc4 = lane & 3;

    const __half* Qg = Q + ((size_t)bh * T_ + q0) * HD_;
    const __half* Kg = K + (size_t)bh * T_ * HD_;
    const __half* Vg = V + (size_t)bh * T_ * HD_;

    // ldmatrix address components
    const int arow = (lane & 7) + ((lane >> 3) & 1) * 8;
    const int akoff = (lane >> 4) * 8;
    const uint32_t qa_off = ((uint32_t)(wm + arow) * LDA + akoff) * 2;
    const int brow = (lane & 7) + ((lane >> 4) << 3);
    const int bkoff = ((lane >> 3) & 1) * 8;
    const uint32_t kb_off = ((uint32_t)brow * LDA + bkoff) * 2;
    const int vrow = (lane & 7) + ((lane >> 3) & 1) * 8;
    const int vcoff = (lane >> 4) * 8;
    const uint32_t vb_off = ((uint32_t)vrow * LDA + vcoff) * 2;

    // gmem cp geometry
    const int gr = tid >> 4;          // 0..15
    const int gc = tid & 15;          // 8-half chunk

    // prologue: Q + K(0) + V(0), one group
    #pragma unroll
    for (int i = 0; i < 8; ++i)
        cp16(sQ + ((uint32_t)(gr + 16 * i) * LDA + gc * 8) * 2,
             Qg + (size_t)(gr + 16 * i) * HD_ + gc * 8);
    #pragma unroll
    for (int i = 0; i < 4; ++i)
        cp16(sK + ((uint32_t)(gr + 16 * i) * LDA + gc * 8) * 2,
             Kg + (size_t)(gr + 16 * i) * HD_ + gc * 8);
    #pragma unroll
    for (int i = 0; i < 4; ++i)
        cp16(sV + ((uint32_t)(gr + 16 * i) * LDA + gc * 8) * 2,
             Vg + (size_t)(gr + 16 * i) * HD_ + gc * 8);
    asm volatile("cp.async.commit_group;" ::: "memory");

    const int ntiles = 2 * (qt + 1);

    float m_i[2] = {-INFINITY, -INFINITY};
    float l_i[2] = {0.0f, 0.0f};
    float oacc[16][4];
    #pragma unroll
    for (int nt = 0; nt < 16; ++nt)
        #pragma unroll
        for (int q = 0; q < 4; ++q) oacc[nt][q] = 0.0f;

    for (int t = 0; t < ntiles; ++t) {
        const int kv0 = t * 64;
        const int st = t & 1;

        // K(t), V(t) ready; all warps done with buffers of iter t-1
        asm volatile("cp.async.wait_group 0;" ::: "memory");
        __syncthreads();

        // prefetch K(t+1), V(t+1) into other stage
        if (t + 1 < ntiles) {
            const __half* kg = Kg + (size_t)(kv0 + 64) * HD_;
            const __half* vg = Vg + (size_t)(kv0 + 64) * HD_;
            const uint32_t kb = sK + (uint32_t)((st ^ 1) * KSTB);
            const uint32_t vb = sV + (uint32_t)((st ^ 1) * KSTB);
            #pragma unroll
            for (int i = 0; i < 4; ++i)
                cp16(kb + ((uint32_t)(gr + 16 * i) * LDA + gc * 8) * 2,
                     kg + (size_t)(gr + 16 * i) * HD_ + gc * 8);
            #pragma unroll
            for (int i = 0; i < 4; ++i)
                cp16(vb + ((uint32_t)(gr + 16 * i) * LDA + gc * 8) * 2,
                     vg + (size_t)(gr + 16 * i) * HD_ + gc * 8);
            asm volatile("cp.async.commit_group;" ::: "memory");
        }

        // ---- S = Q @ K^T : warp computes 16 x 64 ----
        float sacc[8][4];
        #pragma unroll
        for (int nt = 0; nt < 8; ++nt)
            #pragma unroll
            for (int q = 0; q < 4; ++q) sacc[nt][q] = 0.0f;

        const uint32_t sKst = sK + (uint32_t)(st * KSTB);
        const uint32_t sVst = sV + (uint32_t)(st * KSTB);
        #pragma unroll
        for (int ks = 0; ks < 8; ++ks) {
            uint32_t a[4], b[4][4];
            LDSM4(a, sQ + qa_off + (uint32_t)(ks * 16) * 2);
            #pragma unroll
            for (int ntp = 0; ntp < 4; ++ntp)
                LDSM4(b[ntp], sKst + kb_off + (uint32_t)(ntp * 16 * LDA + ks * 16) * 2);
            #pragma unroll
            for (int nt = 0; nt < 8; ++nt)
                mma_f16(sacc[nt], a, b[nt >> 1] + (nt & 1) * 2);
        }

        // causal mask (diagonal-region tiles only)
        if (t >= 2 * qt) {
            #pragma unroll
            for (int nt = 0; nt < 8; ++nt)
                #pragma unroll
                for (int q = 0; q < 4; ++q) {
                    const int row = q0 + wm + (q >> 1) * 8 + lr4;
                    const int col = kv0 + nt * 8 + lc4 * 2 + (q & 1);
                    if (col > row) sacc[nt][q] = -1e30f;
                }
        }

        // ---- intra-warp online softmax (rows lr4, lr4+8) ----
        float pmax[2] = {-INFINITY, -INFINITY};
        #pragma unroll
        for (int nt = 0; nt < 8; ++nt)
            #pragma unroll
            for (int q = 0; q < 4; ++q)
                pmax[q >> 1] = fmaxf(pmax[q >> 1], sacc[nt][q]);
        #pragma unroll
        for (int r = 0; r < 2; ++r) {
            pmax[r] = fmaxf(pmax[r], __shfl_xor_sync(0xffffffffu, pmax[r], 1));
            pmax[r] = fmaxf(pmax[r], __shfl_xor_sync(0xffffffffu, pmax[r], 2));
        }
        float corr[2], psum[2];
        #pragma unroll
        for (int r = 0; r < 2; ++r) {
            const float mnew = fmaxf(m_i[r], pmax[r]);
            corr[r] = __expf(m_i[r] - mnew);
            m_i[r] = mnew;
            psum[r] = 0.0f;
        }
        #pragma unroll
        for (int nt = 0; nt < 8; ++nt)
            #pragma unroll
            for (int q = 0; q < 4; ++q) {
                const float p = __expf(sacc[nt][q] - m_i[q >> 1]);
                sacc[nt][q] = p;
                psum[q >> 1] += p;
            }
        #pragma unroll
        for (int r = 0; r < 2; ++r) {
            psum[r] += __shfl_xor_sync(0xffffffffu, psum[r], 1);
            psum[r] += __shfl_xor_sync(0xffffffffu, psum[r], 2);
            l_i[r] = l_i[r] * corr[r] + psum[r];
        }
        #pragma unroll
        for (int nt = 0; nt < 16; ++nt)
            #pragma unroll
            for (int q = 0; q < 4; ++q)
                oacc[nt][q] *= corr[q >> 1];

        // ---- pack P accumulators into PV A-operand fragments (registers) ----
        uint32_t pa[4][4];
        #pragma unroll
        for (int ks = 0; ks < 4; ++ks) {
            pa[ks][0] = packh2(sacc[2 * ks][0],     sacc[2 * ks][1]);
            pa[ks][1] = packh2(sacc[2 * ks][2],     sacc[2 * ks][3]);
            pa[ks][2] = packh2(sacc[2 * ks + 1][0], sacc[2 * ks + 1][1]);
            pa[ks][3] = packh2(sacc[2 * ks + 1][2], sacc[2 * ks + 1][3]);
        }

        // ---- O += P @ V : 16 rows x 128 hd cols ----
        #pragma unroll
        for (int ks = 0; ks < 4; ++ks) {
            uint32_t vb[8][4];
            #pragma unroll
            for (int ntq = 0; ntq < 8; ++ntq)
                LDSM4T(vb[ntq], sVst + vb_off + (uint32_t)(ks * 16 * LDA + ntq * 16) * 2);
            #pragma unroll
            for (int nt = 0; nt < 16; ++nt)
                mma_f16(oacc[nt], pa[ks], vb[nt >> 1] + (nt & 1) * 2);
        }
    }

    // epilogue: normalize, fp16 store
    #pragma unroll
    for (int h = 0; h < 2; ++h) {
        const int row = q0 + wm + h * 8 + lr4;
        const float inv = 1.0f / l_i[h];
        __half* op = Out + ((size_t)bz * T_ + row) * D_ + head * HD_ + lc4 * 2;
        #pragma unroll
        for (int nt = 0; nt < 16; ++nt)
            *(__half2*)(op + nt * 8) =
                __floats2half2_rn(oacc[nt][h * 2] * inv, oacc[nt][h * 2 + 1] * inv);
    }
}

// ---------------------------------------------------------------------------
// Launch
// ---------------------------------------------------------------------------
extern "C" void kernel_launch(void* const* d_in, const int* in_sizes, int n_in,
                              void* d_out, int out_size)
{
    const float* x  = (const float*)d_in[0];
    const float* wn = (const float*)d_in[2];
    const float* wq = (const float*)d_in[3];
    const float* wk = (const float*)d_in[4];
    const float* wv = (const float*)d_in[5];
    const float* wo = (const float*)d_in[6];
    float* out = (float*)d_out;

    __half* base = nullptr;
    cudaGetSymbolAddress((void**)&base, g_scratch_h);
    __half* xn  = base;
    __half* qkv = base + 1ull * BTD_;
    __half* qb  = qkv;
    __half* kb  = base + 2ull * BTD_;
    __half* vb  = base + 3ull * BTD_;
    __half* ao  = base + 4ull * BTD_;
    __half* rw  = base + 5ull * BTD_;
    __half* rwq = rw;
    __half* rwk = rw + 1ull * DD_;
    __half* rwv = rw + 2ull * DD_;
    __half* rwo = rw + 3ull * DD_;

    cudaFuncSetAttribute(gemm_qkv, cudaFuncAttributeMaxDynamicSharedMemorySize,
                         GEMM_SMEM_BYTES);
    cudaFuncSetAttribute(gemm_out, cudaFuncAttributeMaxDynamicSharedMemorySize,
                         GEMM_SMEM_BYTES);
    cudaFuncSetAttribute(attn_mma, cudaFuncAttributeMaxDynamicSharedMemorySize,
                         ATT_SMEM_BYTES);

    round4_kernel<<<4 * (DD_ / 4 / 256), 256>>>(
        (const float4*)wq, (const float4*)wk, (const float4*)wv, (const float4*)wo, rw);

    rmsnorm_kernel<<<BT_, 256>>>(x, wn, xn);

    gemm_qkv<<<dim3(48, BT_ / 128), 256, GEMM_SMEM_BYTES>>>(xn, rwq, rwk, rwv, qkv);

    attn_mma<<<dim3(T_ / 128, B_ * H_), 256, ATT_SMEM_BYTES>>>(qb, kb, vb, ao);

    gemm_out<<<dim3(D_ / 128, BT_ / 128), 256, GEMM_SMEM_BYTES>>>(ao, rwo, out);
}

// round 9
// speedup vs baseline: 9.1750x; 1.0221x over previous
#include <cuda_runtime.h>
#include <cuda_fp16.h>
#include <math.h>
#include <stdint.h>

#define B_ 2
#define T_ 2048
#define D_ 2048
#define H_ 16
#define HD_ 128
#define BT_ (B_ * T_)
#define BTD_ (B_ * T_ * D_)
#define DD_ (D_ * D_)

// Scratch (halves): xn, q, k, v, attn_out (5 x BTD) + 4 fp16 weights (4 x DD)
__device__ __half g_scratch_h[5ull * BTD_ + 4ull * DD_];

// ---------------------------------------------------------------------------
// helpers
// ---------------------------------------------------------------------------
__device__ __forceinline__ uint32_t smem_u32(const void* p) {
    uint32_t a;
    asm("{ .reg .u64 t; cvta.to.shared.u64 t, %1; cvt.u32.u64 %0, t; }"
        : "=r"(a) : "l"(p));
    return a;
}

__device__ __forceinline__ void cp16(uint32_t s, const void* g) {
    asm volatile("cp.async.cg.shared.global [%0], [%1], 16;"
                 :: "r"(s), "l"(g) : "memory");
}

#define LDSM4(R, addr) \
    asm volatile("ldmatrix.sync.aligned.m8n8.x4.shared.b16 {%0,%1,%2,%3}, [%4];" \
        : "=r"((R)[0]), "=r"((R)[1]), "=r"((R)[2]), "=r"((R)[3]) : "r"(addr))

#define LDSM4T(R, addr) \
    asm volatile("ldmatrix.sync.aligned.m8n8.x4.trans.shared.b16 {%0,%1,%2,%3}, [%4];" \
        : "=r"((R)[0]), "=r"((R)[1]), "=r"((R)[2]), "=r"((R)[3]) : "r"(addr))

__device__ __forceinline__ void mma_f16(float* c, const uint32_t* a, const uint32_t* b) {
    asm volatile(
        "mma.sync.aligned.m16n8k16.row.col.f32.f16.f16.f32 "
        "{%0,%1,%2,%3}, {%4,%5,%6,%7}, {%8,%9}, {%0,%1,%2,%3};"
        : "+f"(c[0]), "+f"(c[1]), "+f"(c[2]), "+f"(c[3])
        : "r"(a[0]), "r"(a[1]), "r"(a[2]), "r"(a[3]), "r"(b[0]), "r"(b[1]));
}

__device__ __forceinline__ uint32_t packh2(float lo, float hi) {
    __half2 h = __floats2half2_rn(lo, hi);
    return *(uint32_t*)&h;
}

// ---------------------------------------------------------------------------
// fp16 pre-rounding of all 4 weight matrices in one launch
// ---------------------------------------------------------------------------
__global__ void __launch_bounds__(256) round4_kernel(
    const float4* __restrict__ s0, const float4* __restrict__ s1,
    const float4* __restrict__ s2, const float4* __restrict__ s3,
    __half* __restrict__ dst)
{
    const int m = blockIdx.x >> 12;
    const int i = (blockIdx.x & 4095) * 256 + threadIdx.x;
    const float4* src = (m == 0) ? s0 : (m == 1) ? s1 : (m == 2) ? s2 : s3;
    float4 v = src[i];
    __half* d = dst + (size_t)m * DD_ + (size_t)i * 4;
    *(__half2*)d       = __floats2half2_rn(v.x, v.y);
    *(__half2*)(d + 2) = __floats2half2_rn(v.z, v.w);
}

// ---------------------------------------------------------------------------
// RMSNorm: one block per row of D=2048; output fp16
// ---------------------------------------------------------------------------
__global__ void __launch_bounds__(256) rmsnorm_kernel(
    const float* __restrict__ x, const float* __restrict__ w, __half* __restrict__ out)
{
    const int row = blockIdx.x;
    const float4* xr = (const float4*)(x + (size_t)row * D_);
    __half* orow = out + (size_t)row * D_;
    const float4* w4 = (const float4*)w;
    const int tid = threadIdx.x;

    float4 v0 = xr[tid];
    float4 v1 = xr[tid + 256];
    float ss = v0.x*v0.x + v0.y*v0.y + v0.z*v0.z + v0.w*v0.w
             + v1.x*v1.x + v1.y*v1.y + v1.z*v1.z + v1.w*v1.w;

    #pragma unroll
    for (int m = 16; m > 0; m >>= 1) ss += __shfl_xor_sync(0xffffffffu, ss, m);

    __shared__ float red[8];
    if ((tid & 31) == 0) red[tid >> 5] = ss;
    __syncthreads();
    float tot = red[0] + red[1] + red[2] + red[3] + red[4] + red[5] + red[6] + red[7];

    const float inv = 1.0f / (sqrtf(tot) * 0.022097086912079612f + 1e-8f);

    float4 w0 = w4[tid], w1 = w4[tid + 256];
    *(__half2*)(orow + tid * 4)     = __floats2half2_rn(v0.x * w0.x * inv, v0.y * w0.y * inv);
    *(__half2*)(orow + tid * 4 + 2) = __floats2half2_rn(v0.z * w0.z * inv, v0.w * w0.w * inv);
    *(__half2*)(orow + (tid + 256) * 4)     = __floats2half2_rn(v1.x * w1.x * inv, v1.y * w1.y * inv);
    *(__half2*)(orow + (tid + 256) * 4 + 2) = __floats2half2_rn(v1.z * w1.z * inv, v1.w * w1.w * inv);
}

// ---------------------------------------------------------------------------
// fp16 mma.sync GEMM core. 128x128x64 CTA tile, 8 warps (2x4), 64x32 warp tile.
// 3-stage cp.async, ldmatrix fragments, m16n8k16.
// ---------------------------------------------------------------------------
#define LDW 72                              // halves per row (64 + 8 pad)
#define AB_BYTES (128 * LDW * 2)            // one matrix per stage: 18432 B
#define STG_BYTES (2 * AB_BYTES)            // 36864 B
#define GEMM_SMEM_BYTES (3 * STG_BYTES)     // 110592 B
#define NKT 32                              // 2048 / 64

struct GemmAcc { float acc[4][4][4]; };

__device__ __forceinline__ void gemm_core(
    const __half* __restrict__ A, const __half* __restrict__ W,
    int bm, int bn, __half* sm, GemmAcc& g)
{
    const int tid = threadIdx.x;
    const int lane = tid & 31;
    const int wid = tid >> 5;
    const int wm = (wid & 1) * 64;
    const int wn = (wid >> 1) * 32;

    const int r0 = tid >> 3;
    const int c8 = tid & 7;
    const __half* Ag = A + (size_t)(bm * 128 + r0) * 2048 + c8 * 8;
    const __half* Wg = W + (size_t)(bn * 128 + r0) * 2048 + c8 * 8;
    const uint32_t sbase = smem_u32(sm);
    uint32_t soff[4];
    #pragma unroll
    for (int i = 0; i < 4; ++i)
        soff[i] = ((uint32_t)(r0 + 32 * i) * LDW + c8 * 8) * 2;

    const int arow = (lane & 7) + ((lane >> 3) & 1) * 8;
    const int akoff = (lane >> 4) * 8;
    const uint32_t a_off = ((uint32_t)(wm + arow) * LDW + akoff) * 2;
    const int brow = (lane & 7) + ((lane >> 4) << 3);
    const int bkoff = ((lane >> 3) & 1) * 8;
    const uint32_t b_off = AB_BYTES + ((uint32_t)(wn + brow) * LDW + bkoff) * 2;

    #pragma unroll
    for (int mt = 0; mt < 4; ++mt)
        #pragma unroll
        for (int nt = 0; nt < 4; ++nt)
            #pragma unroll
            for (int q = 0; q < 4; ++q) g.acc[mt][nt][q] = 0.0f;

    #pragma unroll
    for (int j = 0; j < 2; ++j) {
        const uint32_t st = sbase + (uint32_t)j * STG_BYTES;
        #pragma unroll
        for (int i = 0; i < 4; ++i) cp16(st + soff[i], Ag + (size_t)(32 * i) * 2048 + j * 64);
        #pragma unroll
        for (int i = 0; i < 4; ++i) cp16(st + AB_BYTES + soff[i], Wg + (size_t)(32 * i) * 2048 + j * 64);
        asm volatile("cp.async.commit_group;" ::: "memory");
    }

    int s = 0;
    for (int kt = 0; kt < NKT; ++kt) {
        if (kt < NKT - 1) asm volatile("cp.async.wait_group 1;" ::: "memory");
        else              asm volatile("cp.async.wait_group 0;" ::: "memory");
        __syncthreads();

        if (kt + 2 < NKT) {
            const int s2 = (s + 2 >= 3) ? s - 1 : s + 2;
            const uint32_t st = sbase + (uint32_t)s2 * STG_BYTES;
            const __half* ag = Ag + (kt + 2) * 64;
            const __half* wg = Wg + (kt + 2) * 64;
            #pragma unroll
            for (int i = 0; i < 4; ++i) cp16(st + soff[i], ag + (size_t)(32 * i) * 2048);
            #pragma unroll
            for (int i = 0; i < 4; ++i) cp16(st + AB_BYTES + soff[i], wg + (size_t)(32 * i) * 2048);
            asm volatile("cp.async.commit_group;" ::: "memory");
        }

        const uint32_t stb = sbase + (uint32_t)s * STG_BYTES;
        #pragma unroll
        for (int ks = 0; ks < 4; ++ks) {
            uint32_t a[4][4], b[2][4];
            #pragma unroll
            for (int mt = 0; mt < 4; ++mt)
                LDSM4(a[mt], stb + a_off + (uint32_t)(mt * 16 * LDW + ks * 16) * 2);
            #pragma unroll
            for (int ntp = 0; ntp < 2; ++ntp)
                LDSM4(b[ntp], stb + b_off + (uint32_t)(ntp * 16 * LDW + ks * 16) * 2);
            #pragma unroll
            for (int mt = 0; mt < 4; ++mt)
                #pragma unroll
                for (int nt = 0; nt < 4; ++nt)
                    mma_f16(g.acc[mt][nt], a[mt], b[nt >> 1] + (nt & 1) * 2);
        }
        s = (s + 1 == 3) ? 0 : s + 1;
    }
}

// softmax scale folded with log2(e): Q pre-scale so exp2f can be used directly
#define ATT_SCALE_L2E 0.12751742688f

// Fused QKV: grid (48, 32); bn>>4 selects weight & output. [B,H,T,HD] fp16.
// Q (sel 0) is pre-scaled by ATT_SCALE_L2E (softmax in exp2 domain).
__global__ void __launch_bounds__(256, 2) gemm_qkv(
    const __half* __restrict__ A, const __half* __restrict__ Wq,
    const __half* __restrict__ Wk, const __half* __restrict__ Wv,
    __half* __restrict__ QKV)
{
    extern __shared__ __half smh[];
    const int bm = blockIdx.y;
    const int sel = blockIdx.x >> 4;
    const int bn = blockIdx.x & 15;
    const __half* W = (sel == 0) ? Wq : (sel == 1) ? Wk : Wv;
    __half* C = QKV + (size_t)sel * BTD_;
    const float scale = (sel == 0) ? ATT_SCALE_L2E : 1.0f;

    GemmAcc g;
    gemm_core(A, W, bm, bn, smh, g);

    const int lane = threadIdx.x & 31;
    const int wid = threadIdx.x >> 5;
    const int wm = (wid & 1) * 64;
    const int wn = (wid >> 1) * 32;
    const int rbase = bm * 128 + wm + (lane >> 2);
    const int cbase = wn + (lane & 3) * 2;
    #pragma unroll
    for (int mt = 0; mt < 4; ++mt)
        #pragma unroll
        for (int half = 0; half < 2; ++half) {
            const int row = rbase + mt * 16 + half * 8;
            const int b = row >> 11;
            const int t = row & (T_ - 1);
            __half* cp = C + (((size_t)(b * H_ + bn)) * T_ + t) * HD_ + cbase;
            #pragma unroll
            for (int nt = 0; nt < 4; ++nt)
                *(__half2*)(cp + nt * 8) =
                    __floats2half2_rn(g.acc[mt][nt][half * 2] * scale,
                                      g.acc[mt][nt][half * 2 + 1] * scale);
        }
}

// Final projection: fp32 row-major store.
__global__ void __launch_bounds__(256, 2) gemm_out(
    const __half* __restrict__ A, const __half* __restrict__ W, float* __restrict__ C)
{
    extern __shared__ __half smh[];
    const int bm = blockIdx.y, bn = blockIdx.x;

    GemmAcc g;
    gemm_core(A, W, bm, bn, smh, g);

    const int lane = threadIdx.x & 31;
    const int wid = threadIdx.x >> 5;
    const int wm = (wid & 1) * 64;
    const int wn = (wid >> 1) * 32;
    const int rbase = bm * 128 + wm + (lane >> 2);
    const int cbase = wn + (lane & 3) * 2;
    #pragma unroll
    for (int mt = 0; mt < 4; ++mt)
        #pragma unroll
        for (int half = 0; half < 2; ++half) {
            const int row = rbase + mt * 16 + half * 8;
            float* cp = C + (size_t)row * D_ + bn * 128 + cbase;
            #pragma unroll
            for (int nt = 0; nt < 4; ++nt)
                *(float2*)(cp + nt * 8) =
                    make_float2(g.acc[mt][nt][half * 2], g.acc[mt][nt][half * 2 + 1]);
        }
}

// ---------------------------------------------------------------------------
// fp16 flash attention, FA2-style. CTA: 128 threads / 4 warps / 64 q-rows
// (16 rows per warp); kv step 64; double-buffered K/V; one sync per tile.
// 87 KB smem + ~45.6K regs per 2 CTAs -> 2 CTAs/SM for cross-CTA overlap.
// Softmax in exp2 domain (Q pre-scaled by scale*log2e).
// ---------------------------------------------------------------------------
#define LDA 136
#define QS_BYTES (64 * LDA * 2)             // 17408
#define KSTB (64 * LDA * 2)                 // 17408
#define KS_B QS_BYTES
#define VS_B (KS_B + 2 * KSTB)
#define ATT_SMEM_BYTES (VS_B + 2 * KSTB)    // 87040

__global__ void __launch_bounds__(128, 2) attn_mma(
    const __half* __restrict__ Q, const __half* __restrict__ K,
    const __half* __restrict__ V, __half* __restrict__ Out)
{
    extern __shared__ __half smh[];
    const uint32_t sbase = smem_u32(smh);
    const uint32_t sQ = sbase;
    const uint32_t sK = sbase + KS_B;
    const uint32_t sV = sbase + VS_B;

    const int qt = (int)gridDim.x - 1 - (int)blockIdx.x;   // heavy tiles first
    const int bh = blockIdx.y;
    const int bz = bh >> 4;
    const int head = bh & (H_ - 1);
    const int q0 = qt * 64;
    const int tid = threadIdx.x;
    const int lane = tid & 31;
    const int wid = tid >> 5;                // 0..3
    const int wm = wid * 16;                 // warp owns q rows [wm, wm+16)
    const int lr4 = lane >> 2;
    const int lc4 = lane & 3;

    const __half* Qg = Q + ((size_t)bh * T_ + q0) * HD_;
    const __half* Kg = K + (size_t)bh * T_ * HD_;
    const __half* Vg = V + (size_t)bh * T_ * HD_;

    // ldmatrix address components
    const int arow = (lane & 7) + ((lane >> 3) & 1) * 8;
    const int akoff = (lane >> 4) * 8;
    const uint32_t qa_off = ((uint32_t)(wm + arow) * LDA + akoff) * 2;
    const int brow = (lane & 7) + ((lane >> 4) << 3);
    const int bkoff = ((lane >> 3) & 1) * 8;
    const uint32_t kb_off = ((uint32_t)brow * LDA + bkoff) * 2;
    const int vrow = (lane & 7) + ((lane >> 3) & 1) * 8;
    const int vcoff = (lane >> 4) * 8;
    const uint32_t vb_off = ((uint32_t)vrow * LDA + vcoff) * 2;

    // gmem cp geometry: 128 threads, 64x128 tile = 1024 16B-chunks, 8/thread
    const int gr = tid >> 4;          // 0..7
    const int gc = tid & 15;          // 8-half chunk

    // prologue: Q + K(0) + V(0)
    #pragma unroll
    for (int i = 0; i < 8; ++i)
        cp16(sQ + ((uint32_t)(gr + 8 * i) * LDA + gc * 8) * 2,
             Qg + (size_t)(gr + 8 * i) * HD_ + gc * 8);
    #pragma unroll
    for (int i = 0; i < 8; ++i)
        cp16(sK + ((uint32_t)(gr + 8 * i) * LDA + gc * 8) * 2,
             Kg + (size_t)(gr + 8 * i) * HD_ + gc * 8);
    #pragma unroll
    for (int i = 0; i < 8; ++i)
        cp16(sV + ((uint32_t)(gr + 8 * i) * LDA + gc * 8) * 2,
             Vg + (size_t)(gr + 8 * i) * HD_ + gc * 8);
    asm volatile("cp.async.commit_group;" ::: "memory");

    const int ntiles = qt + 1;

    float m_i[2] = {-INFINITY, -INFINITY};
    float l_i[2] = {0.0f, 0.0f};
    float oacc[16][4];
    #pragma unroll
    for (int nt = 0; nt < 16; ++nt)
        #pragma unroll
        for (int q = 0; q < 4; ++q) oacc[nt][q] = 0.0f;

    for (int t = 0; t < ntiles; ++t) {
        const int kv0 = t * 64;
        const int st = t & 1;

        asm volatile("cp.async.wait_group 0;" ::: "memory");
        __syncthreads();

        // prefetch K(t+1), V(t+1)
        if (t + 1 < ntiles) {
            const __half* kg = Kg + (size_t)(kv0 + 64) * HD_;
            const __half* vg = Vg + (size_t)(kv0 + 64) * HD_;
            const uint32_t kb = sK + (uint32_t)((st ^ 1) * KSTB);
            const uint32_t vb = sV + (uint32_t)((st ^ 1) * KSTB);
            #pragma unroll
            for (int i = 0; i < 8; ++i)
                cp16(kb + ((uint32_t)(gr + 8 * i) * LDA + gc * 8) * 2,
                     kg + (size_t)(gr + 8 * i) * HD_ + gc * 8);
            #pragma unroll
            for (int i = 0; i < 8; ++i)
                cp16(vb + ((uint32_t)(gr + 8 * i) * LDA + gc * 8) * 2,
                     vg + (size_t)(gr + 8 * i) * HD_ + gc * 8);
            asm volatile("cp.async.commit_group;" ::: "memory");
        }

        // ---- S = Q @ K^T : warp computes 16 x 64 ----
        float sacc[8][4];
        #pragma unroll
        for (int nt = 0; nt < 8; ++nt)
            #pragma unroll
            for (int q = 0; q < 4; ++q) sacc[nt][q] = 0.0f;

        const uint32_t sKst = sK + (uint32_t)(st * KSTB);
        const uint32_t sVst = sV + (uint32_t)(st * KSTB);
        #pragma unroll
        for (int ks = 0; ks < 8; ++ks) {
            uint32_t a[4], b[4][4];
            LDSM4(a, sQ + qa_off + (uint32_t)(ks * 16) * 2);
            #pragma unroll
            for (int ntp = 0; ntp < 4; ++ntp)
                LDSM4(b[ntp], sKst + kb_off + (uint32_t)(ntp * 16 * LDA + ks * 16) * 2);
            #pragma unroll
            for (int nt = 0; nt < 8; ++nt)
                mma_f16(sacc[nt], a, b[nt >> 1] + (nt & 1) * 2);
        }

        // causal mask (diagonal tile only; q0 == kv0 there)
        if (t == qt) {
            #pragma unroll
            for (int nt = 0; nt < 8; ++nt)
                #pragma unroll
                for (int q = 0; q < 4; ++q) {
                    const int row = wm + (q >> 1) * 8 + lr4;
                    const int col = nt * 8 + lc4 * 2 + (q & 1);
                    if (col > row) sacc[nt][q] = -1e30f;
                }
        }

        // ---- intra-warp online softmax (exp2 domain) ----
        float pmax[2] = {-INFINITY, -INFINITY};
        #pragma unroll
        for (int nt = 0; nt < 8; ++nt)
            #pragma unroll
            for (int q = 0; q < 4; ++q)
                pmax[q >> 1] = fmaxf(pmax[q >> 1], sacc[nt][q]);
        #pragma unroll
        for (int r = 0; r < 2; ++r) {
            pmax[r] = fmaxf(pmax[r], __shfl_xor_sync(0xffffffffu, pmax[r], 1));
            pmax[r] = fmaxf(pmax[r], __shfl_xor_sync(0xffffffffu, pmax[r], 2));
        }
        float corr[2], psum[2];
        #pragma unroll
        for (int r = 0; r < 2; ++r) {
            const float mnew = fmaxf(m_i[r], pmax[r]);
            corr[r] = exp2f(m_i[r] - mnew);
            m_i[r] = mnew;
            psum[r] = 0.0f;
        }
        #pragma unroll
        for (int nt = 0; nt < 8; ++nt)
            #pragma unroll
            for (int q = 0; q < 4; ++q) {
                const float p = exp2f(sacc[nt][q] - m_i[q >> 1]);
                sacc[nt][q] = p;
                psum[q >> 1] += p;
            }
        #pragma unroll
        for (int r = 0; r < 2; ++r) {
            psum[r] += __shfl_xor_sync(0xffffffffu, psum[r], 1);
            psum[r] += __shfl_xor_sync(0xffffffffu, psum[r], 2);
            l_i[r] = l_i[r] * corr[r] + psum[r];
        }
        #pragma unroll
        for (int nt = 0; nt < 16; ++nt)
            #pragma unroll
            for (int q = 0; q < 4; ++q)
                oacc[nt][q] *= corr[q >> 1];

        // ---- pack P accumulators into PV A-operand fragments (registers) ----
        uint32_t pa[4][4];
        #pragma unroll
        for (int ks = 0; ks < 4; ++ks) {
            pa[ks][0] = packh2(sacc[2 * ks][0],     sacc[2 * ks][1]);
            pa[ks][1] = packh2(sacc[2 * ks][2],     sacc[2 * ks][3]);
            pa[ks][2] = packh2(sacc[2 * ks + 1][0], sacc[2 * ks + 1][1]);
            pa[ks][3] = packh2(sacc[2 * ks + 1][2], sacc[2 * ks + 1][3]);
        }

        // ---- O += P @ V : 16 rows x 128 hd cols ----
        #pragma unroll
        for (int ks = 0; ks < 4; ++ks) {
            uint32_t vb[8][4];
            #pragma unroll
            for (int ntq = 0; ntq < 8; ++ntq)
                LDSM4T(vb[ntq], sVst + vb_off + (uint32_t)(ks * 16 * LDA + ntq * 16) * 2);
            #pragma unroll
            for (int nt = 0; nt < 16; ++nt)
                mma_f16(oacc[nt], pa[ks], vb[nt >> 1] + (nt & 1) * 2);
        }
    }

    // epilogue: normalize, fp16 store
    #pragma unroll
    for (int h = 0; h < 2; ++h) {
        const int row = q0 + wm + h * 8 + lr4;
        const float inv = 1.0f / l_i[h];
        __half* op = Out + ((size_t)bz * T_ + row) * D_ + head * HD_ + lc4 * 2;
        #pragma unroll
        for (int nt = 0; nt < 16; ++nt)
            *(__half2*)(op + nt * 8) =
                __floats2half2_rn(oacc[nt][h * 2] * inv, oacc[nt][h * 2 + 1] * inv);
    }
}

// ---------------------------------------------------------------------------
// Launch
// ---------------------------------------------------------------------------
extern "C" void kernel_launch(void* const* d_in, const int* in_sizes, int n_in,
                              void* d_out, int out_size)
{
    const float* x  = (const float*)d_in[0];
    const float* wn = (const float*)d_in[2];
    const float* wq = (const float*)d_in[3];
    const float* wk = (const float*)d_in[4];
    const float* wv = (const float*)d_in[5];
    const float* wo = (const float*)d_in[6];
    float* out = (float*)d_out;

    __half* base = nullptr;
    cudaGetSymbolAddress((void**)&base, g_scratch_h);
    __half* xn  = base;
    __half* qkv = base + 1ull * BTD_;
    __half* qb  = qkv;
    __half* kb  = base + 2ull * BTD_;
    __half* vb  = base + 3ull * BTD_;
    __half* ao  = base + 4ull * BTD_;
    __half* rw  = base + 5ull * BTD_;
    __half* rwq = rw;
    __half* rwk = rw + 1ull * DD_;
    __half* rwv = rw + 2ull * DD_;
    __half* rwo = rw + 3ull * DD_;

    cudaFuncSetAttribute(gemm_qkv, cudaFuncAttributeMaxDynamicSharedMemorySize,
                         GEMM_SMEM_BYTES);
    cudaFuncSetAttribute(gemm_out, cudaFuncAttributeMaxDynamicSharedMemorySize,
                         GEMM_SMEM_BYTES);
    cudaFuncSetAttribute(attn_mma, cudaFuncAttributeMaxDynamicSharedMemorySize,
                         ATT_SMEM_BYTES);

    round4_kernel<<<4 * (DD_ / 4 / 256), 256>>>(
        (const float4*)wq, (const float4*)wk, (const float4*)wv, (const float4*)wo, rw);

    rmsnorm_kernel<<<BT_, 256>>>(x, wn, xn);

    gemm_qkv<<<dim3(48, BT_ / 128), 256, GEMM_SMEM_BYTES>>>(xn, rwq, rwk, rwv, qkv);

    attn_mma<<<dim3(T_ / 64, B_ * H_), 128, ATT_SMEM_BYTES>>>(qb, kb, vb, ao);

    gemm_out<<<dim3(D_ / 128, BT_ / 128), 256, GEMM_SMEM_BYTES>>>(ao, rwo, out);
}